// round 9
// baseline (speedup 1.0000x reference)
#include <cuda_runtime.h>
#include <cuda_bf16.h>
#include <cstdint>

#define NN 100000
#define NE 600000
#define DD 128
#define NL 4
#define NT2 1563          // ceil(NN/64)
#define NBLK 391          // ceil(NN/256)

#define RS 272            // padded row stride bytes (136 bf16)
#define ABUF 17408        // 64*272
#define WBUF 34816        // 128*272
#define WMAT 69632        // hi+lo image per matrix
#define SMEM_BYTES (2 * ABUF + 2 * WBUF)   // 104448

// ---------------- scratch (device globals) ---------------------------------
__device__ float g_h[NN * DD];
__device__ float g_y[NN * DD];
__device__ float g_sumL[NL][DD];
__device__ float g_sumsqL[NL][DD];
__device__ int   g_cnt[NN];       // invariant: zero at kernel_launch entry
__device__ int   g_off[NN + 1];
__device__ int   g_bsum[512];
__device__ int   g_cur[NN];
__device__ int   g_scanctr;       // invariant: zero at kernel_launch entry
__device__ uint2 g_edges[NE];     // (src, ea bits) sorted by dst
__device__ unsigned char g_wt[8 * WMAT];   // pre-tiled bf16 hi|lo weight images

__device__ __forceinline__ float relu(float v) { return fmaxf(v, 0.0f); }

__device__ __forceinline__ uint32_t smem_u32(const void* p) {
    uint32_t a;
    asm("{ .reg .u64 t; cvta.to.shared.u64 t, %1; cvt.u32.u64 %0, t; }" : "=r"(a) : "l"(p));
    return a;
}

__device__ __forceinline__ void split2(float x, float y, uint32_t& h, uint32_t& l) {
    __nv_bfloat16 hx = __float2bfloat16_rn(x), hy = __float2bfloat16_rn(y);
    __nv_bfloat16 lx = __float2bfloat16_rn(x - __bfloat162float(hx));
    __nv_bfloat16 ly = __float2bfloat16_rn(y - __bfloat162float(hy));
    __nv_bfloat162 hp = __halves2bfloat162(hx, hy);
    __nv_bfloat162 lp = __halves2bfloat162(lx, ly);
    h = *reinterpret_cast<uint32_t*>(&hp);
    l = *reinterpret_cast<uint32_t*>(&lp);
}

#define LDSM_X4(r, a) \
    asm volatile("ldmatrix.sync.aligned.m8n8.x4.shared.b16 {%0,%1,%2,%3}, [%4];" \
        : "=r"((r)[0]), "=r"((r)[1]), "=r"((r)[2]), "=r"((r)[3]) : "r"(a))

#define LDSM_X4_T(r, a) \
    asm volatile("ldmatrix.sync.aligned.m8n8.x4.trans.shared.b16 {%0,%1,%2,%3}, [%4];" \
        : "=r"((r)[0]), "=r"((r)[1]), "=r"((r)[2]), "=r"((r)[3]) : "r"(a))

#define MMA_BF16(c, a, b0, b1) \
    asm volatile("mma.sync.aligned.m16n8k16.row.col.f32.bf16.bf16.f32 " \
        "{%0,%1,%2,%3},{%4,%5,%6,%7},{%8,%9},{%0,%1,%2,%3};" \
        : "+f"((c)[0]), "+f"((c)[1]), "+f"((c)[2]), "+f"((c)[3]) \
        : "r"((a)[0]), "r"((a)[1]), "r"((a)[2]), "r"((a)[3]), "r"(b0), "r"(b1))

#define CP_ASYNC16(d, s) \
    asm volatile("cp.async.ca.shared.global [%0], [%1], 16;" :: "r"(d), "l"(s))

// =================== preprocessing (3 launches) =============================
// 1) histogram (g_cnt was zeroed by previous replay's k_scan / static init),
//    zero per-layer stats, pre-tile all 8 weight matrices.
__global__ void k_pre1(const int* __restrict__ dst,
                       const float* __restrict__ W1, const float* __restrict__ W2) {
    int gid = blockIdx.x * blockDim.x + threadIdx.x;
    if (gid < NE) atomicAdd(&g_cnt[dst[gid]], 1);
    if (gid < NL * DD) {
        (&g_sumL[0][0])[gid] = 0.0f;
        (&g_sumsqL[0][0])[gid] = 0.0f;
    }
    if (gid < 32768) {               // 8 matrices x 4096 float4
        int m = gid >> 12;
        int rem = gid & 4095;
        int r = rem >> 5, c4 = rem & 31;
        const float* Wsrc = ((m & 1) ? W2 : W1) + (size_t)(m >> 1) * DD * DD;
        float4 v = reinterpret_cast<const float4*>(Wsrc + (size_t)r * DD)[c4];
        uint2 h2, l2;
        split2(v.x, v.y, h2.x, l2.x);
        split2(v.z, v.w, h2.y, l2.y);
        unsigned char* base = g_wt + (size_t)m * WMAT;
        *reinterpret_cast<uint2*>(base + r * RS + c4 * 8) = h2;
        *reinterpret_cast<uint2*>(base + WBUF + r * RS + c4 * 8) = l2;
    }
}

// 2) single-kernel exclusive scan (all NBLK blocks resident). Restores g_cnt=0.
__global__ void k_scan() {
    __shared__ int sh[256];
    __shared__ int sh2[256];
    const int b = blockIdx.x, t = threadIdx.x;
    const int i = b * 256 + t;
    int v = (i < NN) ? g_cnt[i] : 0;
    if (i < NN) g_cnt[i] = 0;                    // restore invariant for next replay
    sh[t] = v;
    __syncthreads();
    for (int s = 1; s < 256; s <<= 1) {
        int u = (t >= s) ? sh[t - s] : 0;
        __syncthreads();
        sh[t] += u;
        __syncthreads();
    }
    if (t == 255) {
        g_bsum[b] = sh[255];
        __threadfence();
        atomicAdd(&g_scanctr, 1);
    }
    if (t == 0) {
        while (atomicAdd(&g_scanctr, 0) < NBLK) { }
        __threadfence();
    }
    __syncthreads();
    int acc = 0;
    for (int j = t; j < b; j += 256) acc += g_bsum[j];
    sh2[t] = acc;
    __syncthreads();
    for (int s = 128; s > 0; s >>= 1) {
        if (t < s) sh2[t] += sh2[t + s];
        __syncthreads();
    }
    int prefix = sh2[0];
    if (i < NN) { g_off[i] = prefix + sh[t] - v; g_cur[i] = 0; }
    if (b == 0 && t == 0) g_off[NN] = NE;
}

// 3) fill CSR edge records; reset scan counter for next replay
__global__ void k_fill(const int* __restrict__ src, const int* __restrict__ dst,
                       const float* __restrict__ ea) {
    int e = blockIdx.x * blockDim.x + threadIdx.x;
    if (e == 0) g_scanctr = 0;
    if (e >= NE) return;
    int d = dst[e];
    int pos = g_off[d] + atomicAdd(&g_cur[d], 1);
    g_edges[pos] = make_uint2((uint32_t)src[e], __float_as_uint(ea[e]));
}

// =================== HMMA GEMM (64-row tiles, 256 thr, 2 CTA/SM) ===========
// MODE 0: A = (1+eps)*h + sum_edges relu(h[src]+ea*We+be); y = A@W1+b1; stats->g_sumL[l]
// MODE 1: scale/shift from g_sumL[l]; A = relu(y*sc+sh); out = relu(A@W2+b2) (+h_prev)
template <int MODE>
__global__ void __launch_bounds__(256, 2) gemm_hmma_kernel(
        const float* __restrict__ Xin,
        int widx,
        const float* __restrict__ bias,
        const float* __restrict__ h_prev,
        float* __restrict__ out,
        int add_prev,
        const float* __restrict__ eps, int l,
        const float* __restrict__ We, const float* __restrict__ be) {
    extern __shared__ __align__(16) char smem[];
    __shared__ __align__(16) float s_scale[DD];
    __shared__ __align__(16) float s_shift[DD];
    char* Ahi = smem;
    char* Whi = smem + 2 * ABUF;
    const int tid = threadIdx.x;       // 256
    const int tile = blockIdx.x;
    const int wid = tid >> 5;
    const int lane = tid & 31;

    // ---- W copy via cp.async (overlaps with A fill below) ----
    {
        const unsigned char* wsrc = g_wt + (size_t)widx * WMAT;
        uint32_t wdst = smem_u32(Whi);
#pragma unroll
        for (int i = 0; i < 17; i++) {
            int idx = i * 256 + tid;   // 4352 x 16B
            CP_ASYNC16(wdst + idx * 16, wsrc + idx * 16);
        }
        asm volatile("cp.async.commit_group;");
    }

    if (MODE == 1 && tid < DD) {
        float mu = g_sumL[l][tid] * (1.0f / NN);
        float var = g_sumsqL[l][tid] * (1.0f / NN) - mu * mu;
        float rs = rsqrtf(var + 1e-5f);
        float sc = We[tid] * rs;                 // We slot = gamma row
        s_scale[tid] = sc;
        s_shift[tid] = fmaf(-mu, sc, be[tid]);   // be slot = beta row
    }
    if (MODE == 1) __syncthreads();

    // ---- A fill ----
    if (MODE == 0) {
        const float4* X4 = reinterpret_cast<const float4*>(Xin);
        float4 w4 = reinterpret_cast<const float4*>(We)[lane];
        float4 b4 = reinterpret_cast<const float4*>(be)[lane];
        float s1 = 1.0f + eps[l];
        for (int rr2 = 0; rr2 < 8; rr2++) {
            int r = wid * 8 + rr2;
            int n = tile * 64 + r;
            float4 acc = make_float4(0.f, 0.f, 0.f, 0.f);
            if (n < NN) {
                float4 hv = X4[(size_t)n * 32 + lane];
                acc.x = s1 * hv.x; acc.y = s1 * hv.y;
                acc.z = s1 * hv.z; acc.w = s1 * hv.w;
                int base = g_off[n];
                int deg = g_off[n + 1] - base;
                int i = 0;
                for (; i + 4 <= deg; i += 4) {
                    uint2 e0 = g_edges[base + i];
                    uint2 e1 = g_edges[base + i + 1];
                    uint2 e2 = g_edges[base + i + 2];
                    uint2 e3 = g_edges[base + i + 3];
                    float4 h0 = X4[(size_t)e0.x * 32 + lane];
                    float4 h1 = X4[(size_t)e1.x * 32 + lane];
                    float4 h2v = X4[(size_t)e2.x * 32 + lane];
                    float4 h3 = X4[(size_t)e3.x * 32 + lane];
                    float a0 = __uint_as_float(e0.y);
                    float a1 = __uint_as_float(e1.y);
                    float a2 = __uint_as_float(e2.y);
                    float a3 = __uint_as_float(e3.y);
                    acc.x += relu(h0.x + fmaf(a0, w4.x, b4.x)) + relu(h1.x + fmaf(a1, w4.x, b4.x))
                           + relu(h2v.x + fmaf(a2, w4.x, b4.x)) + relu(h3.x + fmaf(a3, w4.x, b4.x));
                    acc.y += relu(h0.y + fmaf(a0, w4.y, b4.y)) + relu(h1.y + fmaf(a1, w4.y, b4.y))
                           + relu(h2v.y + fmaf(a2, w4.y, b4.y)) + relu(h3.y + fmaf(a3, w4.y, b4.y));
                    acc.z += relu(h0.z + fmaf(a0, w4.z, b4.z)) + relu(h1.z + fmaf(a1, w4.z, b4.z))
                           + relu(h2v.z + fmaf(a2, w4.z, b4.z)) + relu(h3.z + fmaf(a3, w4.z, b4.z));
                    acc.w += relu(h0.w + fmaf(a0, w4.w, b4.w)) + relu(h1.w + fmaf(a1, w4.w, b4.w))
                           + relu(h2v.w + fmaf(a2, w4.w, b4.w)) + relu(h3.w + fmaf(a3, w4.w, b4.w));
                }
                for (; i < deg; i++) {
                    uint2 e0 = g_edges[base + i];
                    float4 h0 = X4[(size_t)e0.x * 32 + lane];
                    float a0 = __uint_as_float(e0.y);
                    acc.x += relu(h0.x + fmaf(a0, w4.x, b4.x));
                    acc.y += relu(h0.y + fmaf(a0, w4.y, b4.y));
                    acc.z += relu(h0.z + fmaf(a0, w4.z, b4.z));
                    acc.w += relu(h0.w + fmaf(a0, w4.w, b4.w));
                }
            }
            uint2 h2, l2;
            split2(acc.x, acc.y, h2.x, l2.x);
            split2(acc.z, acc.w, h2.y, l2.y);
            *reinterpret_cast<uint2*>(Ahi + r * RS + lane * 8) = h2;
            *reinterpret_cast<uint2*>(Ahi + ABUF + r * RS + lane * 8) = l2;
        }
    } else {
        for (int i = tid; i < 2048; i += 256) {
            int r = i >> 5, c4 = i & 31;
            int grow = tile * 64 + r;
            float4 v = make_float4(0.f, 0.f, 0.f, 0.f);
            if (grow < NN) {
                v = reinterpret_cast<const float4*>(Xin + (size_t)grow * DD)[c4];
                float4 sc = reinterpret_cast<const float4*>(s_scale)[c4];
                float4 sh = reinterpret_cast<const float4*>(s_shift)[c4];
                v.x = relu(fmaf(v.x, sc.x, sh.x));
                v.y = relu(fmaf(v.y, sc.y, sh.y));
                v.z = relu(fmaf(v.z, sc.z, sh.z));
                v.w = relu(fmaf(v.w, sc.w, sh.w));
            }
            uint2 h2, l2;
            split2(v.x, v.y, h2.x, l2.x);
            split2(v.z, v.w, h2.y, l2.y);
            *reinterpret_cast<uint2*>(Ahi + r * RS + c4 * 8) = h2;
            *reinterpret_cast<uint2*>(Ahi + ABUF + r * RS + c4 * 8) = l2;
        }
    }
    asm volatile("cp.async.wait_group 0;");
    __syncthreads();

    // ---- MMA: 8 warps, each 32 rows x 32 cols ----
    const int warp_m = wid & 1;
    const int warp_n = wid >> 1;
    const int j = lane >> 3;
    const int rr = lane & 7;
    const uint32_t sA = smem_u32(Ahi);
    const uint32_t sW = smem_u32(Whi);

    uint32_t aaddr[2];
#pragma unroll
    for (int mt = 0; mt < 2; mt++)
        aaddr[mt] = sA + (uint32_t)((warp_m * 32 + mt * 16 + (j & 1) * 8 + rr) * RS + (j >> 1) * 16);
    uint32_t baddr[2];
#pragma unroll
    for (int p = 0; p < 2; p++)
        baddr[p] = sW + (uint32_t)(((j & 1) * 8 + rr) * RS + (warp_n * 32 + p * 16 + (j >> 1) * 8) * 2);

    float acc[2][4][4];
#pragma unroll
    for (int mt = 0; mt < 2; mt++)
#pragma unroll
        for (int nt = 0; nt < 4; nt++)
#pragma unroll
            for (int q = 0; q < 4; q++) acc[mt][nt][q] = 0.0f;

#pragma unroll
    for (int ks = 0; ks < 8; ks++) {
        uint32_t ah[2][4], al[2][4], bh[2][4], bl[2][4];
#pragma unroll
        for (int mt = 0; mt < 2; mt++) {
            LDSM_X4(ah[mt], aaddr[mt]);
            LDSM_X4(al[mt], aaddr[mt] + ABUF);
            aaddr[mt] += 32;
        }
#pragma unroll
        for (int p = 0; p < 2; p++) {
            LDSM_X4_T(bh[p], baddr[p]);
            LDSM_X4_T(bl[p], baddr[p] + WBUF);
            baddr[p] += 16 * RS;
        }
#pragma unroll
        for (int mt = 0; mt < 2; mt++)
#pragma unroll
            for (int nt = 0; nt < 4; nt++) {
                const int p = nt >> 1, t2 = (nt & 1) * 2;
                MMA_BF16(acc[mt][nt], ah[mt], bh[p][t2], bh[p][t2 + 1]);
                MMA_BF16(acc[mt][nt], ah[mt], bl[p][t2], bl[p][t2 + 1]);
                MMA_BF16(acc[mt][nt], al[mt], bh[p][t2], bh[p][t2 + 1]);
            }
    }

    // ---- epilogue ----
    float* ssum = reinterpret_cast<float*>(smem);    // reuse A region
    if (MODE == 0) {
        __syncthreads();
        if (tid < 256) ssum[tid] = 0.0f;
        __syncthreads();
    }

    float sv[8], qv[8];
#pragma unroll
    for (int i = 0; i < 8; i++) { sv[i] = 0.0f; qv[i] = 0.0f; }

#pragma unroll
    for (int mt = 0; mt < 2; mt++) {
#pragma unroll
        for (int nt = 0; nt < 4; nt++) {
            int row = tile * 64 + warp_m * 32 + mt * 16 + (lane >> 2);
            int col = warp_n * 32 + nt * 8 + (lane & 3) * 2;
            float2 bv = *reinterpret_cast<const float2*>(bias + col);
#pragma unroll
            for (int hh = 0; hh < 2; hh++) {
                int grow = row + hh * 8;
                if (grow < NN) {
                    float2 o;
                    o.x = acc[mt][nt][hh * 2 + 0] + bv.x;
                    o.y = acc[mt][nt][hh * 2 + 1] + bv.y;
                    if (MODE == 0) {
                        sv[nt * 2 + 0] += o.x; qv[nt * 2 + 0] += o.x * o.x;
                        sv[nt * 2 + 1] += o.y; qv[nt * 2 + 1] += o.y * o.y;
                    } else {
                        o.x = relu(o.x); o.y = relu(o.y);
                        if (add_prev) {
                            float2 hp = *reinterpret_cast<const float2*>(
                                h_prev + (size_t)grow * DD + col);
                            o.x += hp.x; o.y += hp.y;
                        }
                    }
                    *reinterpret_cast<float2*>(out + (size_t)grow * DD + col) = o;
                }
            }
        }
    }

    if (MODE == 0) {
#pragma unroll
        for (int i = 0; i < 8; i++) {
#pragma unroll
            for (int k = 4; k < 32; k <<= 1) {
                sv[i] += __shfl_xor_sync(0xffffffff, sv[i], k);
                qv[i] += __shfl_xor_sync(0xffffffff, qv[i], k);
            }
        }
        if (lane < 4) {
#pragma unroll
            for (int i = 0; i < 8; i++) {
                int col = warp_n * 32 + (i >> 1) * 8 + lane * 2 + (i & 1);
                atomicAdd(&ssum[col], sv[i]);
                atomicAdd(&ssum[128 + col], qv[i]);
            }
        }
        __syncthreads();
        if (tid < 128) {
            atomicAdd(&g_sumL[l][tid], ssum[tid]);
            atomicAdd(&g_sumsqL[l][tid], ssum[128 + tid]);
        }
    }
}

// ---------------- launch ---------------------------------------------------
extern "C" void kernel_launch(void* const* d_in, const int* in_sizes, int n_in,
                              void* d_out, int out_size) {
    const float* x     = (const float*)d_in[0];
    const int* ei      = (const int*)d_in[1];
    const float* ea    = (const float*)d_in[2];
    const float* We    = (const float*)d_in[3];
    const float* be    = (const float*)d_in[4];
    const float* eps   = (const float*)d_in[5];
    const float* W1    = (const float*)d_in[6];
    const float* b1    = (const float*)d_in[7];
    const float* gamma = (const float*)d_in[8];
    const float* beta  = (const float*)d_in[9];
    const float* W2    = (const float*)d_in[10];
    const float* b2    = (const float*)d_in[11];
    float* out         = (float*)d_out;

    float *hbuf, *ybuf;
    cudaGetSymbolAddress((void**)&hbuf, g_h);
    cudaGetSymbolAddress((void**)&ybuf, g_y);

    cudaFuncSetAttribute(gemm_hmma_kernel<0>, cudaFuncAttributeMaxDynamicSharedMemorySize, SMEM_BYTES);
    cudaFuncSetAttribute(gemm_hmma_kernel<1>, cudaFuncAttributeMaxDynamicSharedMemorySize, SMEM_BYTES);

    const int* src = ei;
    const int* dst = ei + NE;

    k_pre1<<<(NE + 255) / 256, 256>>>(dst, W1, W2);
    k_scan<<<NBLK, 256>>>();
    k_fill<<<(NE + 255) / 256, 256>>>(src, dst, ea);

    for (int l = 0; l < NL; l++) {
        const float* h_in = (l == 0) ? x : hbuf;
        float* h_out = (l == NL - 1) ? out : hbuf;

        gemm_hmma_kernel<0><<<NT2, 256, SMEM_BYTES>>>(
            h_in, l * 2, b1 + l * DD, nullptr, ybuf, 0,
            eps, l, We + l * DD, be + l * DD);

        gemm_hmma_kernel<1><<<NT2, 256, SMEM_BYTES>>>(
            ybuf, l * 2 + 1, b2 + l * DD, hbuf, h_out,
            (l > 0) ? 1 : 0, eps, l, gamma + l * DD, beta + l * DD);
    }
}

// round 10
// speedup vs baseline: 1.4865x; 1.4865x over previous
#include <cuda_runtime.h>
#include <cuda_bf16.h>
#include <cstdint>

#define NN 100000
#define NE 600000
#define DD 128
#define NL 4
#define NT2 1563          // ceil(NN/64)

#define RS 272            // padded row stride bytes (136 bf16)
#define ABUF 17408        // 64*272
#define WBUF 34816        // 128*272
#define WMAT 69632        // hi+lo image per matrix
#define SMEM_BYTES (2 * ABUF + 2 * WBUF)   // 104448

// ---------------- scratch (device globals) ---------------------------------
__device__ float g_h[NN * DD];
__device__ float g_agg[NN * DD];
__device__ float g_y[NN * DD];
__device__ float g_sumL[NL][DD];
__device__ float g_sumsqL[NL][DD];
__device__ int   g_cnt[NN];
__device__ int   g_off[NN + 1];
__device__ int   g_bsum[512];
__device__ int   g_cur[NN];
__device__ uint2 g_edges[NE];     // (src, ea bits) sorted by dst
__device__ unsigned char g_wt[8 * WMAT];   // pre-tiled bf16 hi|lo weight images

__device__ __forceinline__ float relu(float v) { return fmaxf(v, 0.0f); }

__device__ __forceinline__ uint32_t smem_u32(const void* p) {
    uint32_t a;
    asm("{ .reg .u64 t; cvta.to.shared.u64 t, %1; cvt.u32.u64 %0, t; }" : "=r"(a) : "l"(p));
    return a;
}

__device__ __forceinline__ void split2(float x, float y, uint32_t& h, uint32_t& l) {
    __nv_bfloat16 hx = __float2bfloat16_rn(x), hy = __float2bfloat16_rn(y);
    __nv_bfloat16 lx = __float2bfloat16_rn(x - __bfloat162float(hx));
    __nv_bfloat16 ly = __float2bfloat16_rn(y - __bfloat162float(hy));
    __nv_bfloat162 hp = __halves2bfloat162(hx, hy);
    __nv_bfloat162 lp = __halves2bfloat162(lx, ly);
    h = *reinterpret_cast<uint32_t*>(&hp);
    l = *reinterpret_cast<uint32_t*>(&lp);
}

#define LDSM_X4(r, a) \
    asm volatile("ldmatrix.sync.aligned.m8n8.x4.shared.b16 {%0,%1,%2,%3}, [%4];" \
        : "=r"((r)[0]), "=r"((r)[1]), "=r"((r)[2]), "=r"((r)[3]) : "r"(a))

#define LDSM_X4_T(r, a) \
    asm volatile("ldmatrix.sync.aligned.m8n8.x4.trans.shared.b16 {%0,%1,%2,%3}, [%4];" \
        : "=r"((r)[0]), "=r"((r)[1]), "=r"((r)[2]), "=r"((r)[3]) : "r"(a))

#define MMA_BF16(c, a, b0, b1) \
    asm volatile("mma.sync.aligned.m16n8k16.row.col.f32.bf16.bf16.f32 " \
        "{%0,%1,%2,%3},{%4,%5,%6,%7},{%8,%9},{%0,%1,%2,%3};" \
        : "+f"((c)[0]), "+f"((c)[1]), "+f"((c)[2]), "+f"((c)[3]) \
        : "r"((a)[0]), "r"((a)[1]), "r"((a)[2]), "r"((a)[3]), "r"(b0), "r"(b1))

#define CP_ASYNC16(d, s) \
    asm volatile("cp.async.ca.shared.global [%0], [%1], 16;" :: "r"(d), "l"(s))

// =================== preprocessing (5 launches, R8-proven) ==================
__global__ void k_zero(const float* __restrict__ W1, const float* __restrict__ W2) {
    int gid = blockIdx.x * blockDim.x + threadIdx.x;
    if (gid < NN) g_cnt[gid] = 0;
    if (gid < NL * DD) {
        (&g_sumL[0][0])[gid] = 0.0f;
        (&g_sumsqL[0][0])[gid] = 0.0f;
    }
    if (gid < 32768) {               // 8 matrices x 4096 float4
        int m = gid >> 12;
        int rem = gid & 4095;
        int r = rem >> 5, c4 = rem & 31;
        const float* Wsrc = ((m & 1) ? W2 : W1) + (size_t)(m >> 1) * DD * DD;
        float4 v = reinterpret_cast<const float4*>(Wsrc + (size_t)r * DD)[c4];
        uint2 h2, l2;
        split2(v.x, v.y, h2.x, l2.x);
        split2(v.z, v.w, h2.y, l2.y);
        unsigned char* base = g_wt + (size_t)m * WMAT;
        *reinterpret_cast<uint2*>(base + r * RS + c4 * 8) = h2;
        *reinterpret_cast<uint2*>(base + WBUF + r * RS + c4 * 8) = l2;
    }
}
__global__ void k_hist(const int* __restrict__ dst) {
    int e = blockIdx.x * blockDim.x + threadIdx.x;
    if (e < NE) atomicAdd(&g_cnt[dst[e]], 1);
}
__global__ void k_scan1() {
    __shared__ int sh[256];
    int t = threadIdx.x;
    int i = blockIdx.x * 256 + t;
    int v = (i < NN) ? g_cnt[i] : 0;
    sh[t] = v;
    __syncthreads();
    for (int s = 1; s < 256; s <<= 1) {
        int u = (t >= s) ? sh[t - s] : 0;
        __syncthreads();
        sh[t] += u;
        __syncthreads();
    }
    if (i < NN) g_off[i] = sh[t] - v;
    if (t == 255) g_bsum[blockIdx.x] = sh[255];
}
__global__ void k_scan2apply() {     // grid nblk, block 256
    __shared__ int sh[256];
    int b = blockIdx.x, t = threadIdx.x;
    int acc = 0;
    for (int i = t; i < b; i += 256) acc += g_bsum[i];
    sh[t] = acc;
    __syncthreads();
    for (int s = 128; s > 0; s >>= 1) {
        if (t < s) sh[t] += sh[t + s];
        __syncthreads();
    }
    int prefix = sh[0];
    int i = b * 256 + t;
    if (i < NN) { g_off[i] += prefix; g_cur[i] = 0; }
    if (b == 0 && t == 0) g_off[NN] = NE;
}
__global__ void k_fill(const int* __restrict__ src, const int* __restrict__ dst,
                       const float* __restrict__ ea) {
    int e = blockIdx.x * blockDim.x + threadIdx.x;
    if (e >= NE) return;
    int d = dst[e];
    int pos = g_off[d] + atomicAdd(&g_cur[d], 1);
    g_edges[pos] = make_uint2((uint32_t)src[e], __float_as_uint(ea[e]));
}

// =================== aggregation: warp per node, high occupancy =============
// agg[n] = (1+eps)*h[n] + sum_{e: dst=n} relu(h[src_e] + ea_e*We + be)
__global__ void __launch_bounds__(256) agg_kernel(
        const float* __restrict__ Xin,
        const float* __restrict__ We, const float* __restrict__ be,
        const float* __restrict__ eps, int l) {
    int n = (blockIdx.x * blockDim.x + threadIdx.x) >> 5;
    int lane = threadIdx.x & 31;
    if (n >= NN) return;
    const float4* X4 = reinterpret_cast<const float4*>(Xin);
    float4 w4 = reinterpret_cast<const float4*>(We)[lane];
    float4 b4 = reinterpret_cast<const float4*>(be)[lane];
    float s1 = 1.0f + eps[l];
    float4 hv = X4[(size_t)n * 32 + lane];
    float4 acc;
    acc.x = s1 * hv.x; acc.y = s1 * hv.y;
    acc.z = s1 * hv.z; acc.w = s1 * hv.w;
    int base = g_off[n];
    int deg = g_off[n + 1] - base;
    int i = 0;
    for (; i + 2 <= deg; i += 2) {
        uint2 e0 = g_edges[base + i];
        uint2 e1 = g_edges[base + i + 1];
        float4 h0 = X4[(size_t)e0.x * 32 + lane];
        float4 h1 = X4[(size_t)e1.x * 32 + lane];
        float a0 = __uint_as_float(e0.y);
        float a1 = __uint_as_float(e1.y);
        acc.x += relu(h0.x + fmaf(a0, w4.x, b4.x)) + relu(h1.x + fmaf(a1, w4.x, b4.x));
        acc.y += relu(h0.y + fmaf(a0, w4.y, b4.y)) + relu(h1.y + fmaf(a1, w4.y, b4.y));
        acc.z += relu(h0.z + fmaf(a0, w4.z, b4.z)) + relu(h1.z + fmaf(a1, w4.z, b4.z));
        acc.w += relu(h0.w + fmaf(a0, w4.w, b4.w)) + relu(h1.w + fmaf(a1, w4.w, b4.w));
    }
    if (i < deg) {
        uint2 e0 = g_edges[base + i];
        float4 h0 = X4[(size_t)e0.x * 32 + lane];
        float a0 = __uint_as_float(e0.y);
        acc.x += relu(h0.x + fmaf(a0, w4.x, b4.x));
        acc.y += relu(h0.y + fmaf(a0, w4.y, b4.y));
        acc.z += relu(h0.z + fmaf(a0, w4.z, b4.z));
        acc.w += relu(h0.w + fmaf(a0, w4.w, b4.w));
    }
    reinterpret_cast<float4*>(g_agg)[(size_t)n * 32 + lane] = acc;
}

// =================== HMMA GEMM (64-row tiles, 256 thr, 2 CTA/SM) ===========
// MODE 0: A = g_agg tile (no transform);   y = A@W1+b1; stats -> g_sumL[l]
// MODE 1: A = relu(y*scale+shift) [BN from g_sumL[l]]; out = relu(A@W2+b2) (+h_prev)
template <int MODE>
__global__ void __launch_bounds__(256, 2) gemm_hmma_kernel(
        const float* __restrict__ Xin,
        int widx,
        const float* __restrict__ bias,
        const float* __restrict__ h_prev,
        float* __restrict__ out,
        int add_prev, int l,
        const float* __restrict__ gamma, const float* __restrict__ beta) {
    extern __shared__ __align__(16) char smem[];
    __shared__ __align__(16) float s_scale[DD];
    __shared__ __align__(16) float s_shift[DD];
    char* Ahi = smem;
    char* Whi = smem + 2 * ABUF;
    const int tid = threadIdx.x;       // 256
    const int tile = blockIdx.x;
    const int wid = tid >> 5;
    const int lane = tid & 31;

    // ---- W copy via cp.async (overlaps with A fill below) ----
    {
        const unsigned char* wsrc = g_wt + (size_t)widx * WMAT;
        uint32_t wdst = smem_u32(Whi);
#pragma unroll
        for (int i = 0; i < 17; i++) {
            int idx = i * 256 + tid;   // 4352 x 16B
            CP_ASYNC16(wdst + idx * 16, wsrc + idx * 16);
        }
        asm volatile("cp.async.commit_group;");
    }

    if (MODE == 1) {
        if (tid < DD) {
            float mu = g_sumL[l][tid] * (1.0f / NN);
            float var = g_sumsqL[l][tid] * (1.0f / NN) - mu * mu;
            float rs = rsqrtf(var + 1e-5f);
            float sc = gamma[tid] * rs;
            s_scale[tid] = sc;
            s_shift[tid] = fmaf(-mu, sc, beta[tid]);
        }
        __syncthreads();
    }

    // ---- A fill (linear, cheap in both modes) ----
    for (int i = tid; i < 2048; i += 256) {
        int r = i >> 5, c4 = i & 31;
        int grow = tile * 64 + r;
        float4 v = make_float4(0.f, 0.f, 0.f, 0.f);
        if (grow < NN) {
            v = reinterpret_cast<const float4*>(Xin + (size_t)grow * DD)[c4];
            if (MODE == 1) {
                float4 sc = reinterpret_cast<const float4*>(s_scale)[c4];
                float4 sh = reinterpret_cast<const float4*>(s_shift)[c4];
                v.x = relu(fmaf(v.x, sc.x, sh.x));
                v.y = relu(fmaf(v.y, sc.y, sh.y));
                v.z = relu(fmaf(v.z, sc.z, sh.z));
                v.w = relu(fmaf(v.w, sc.w, sh.w));
            }
        }
        uint2 h2, l2;
        split2(v.x, v.y, h2.x, l2.x);
        split2(v.z, v.w, h2.y, l2.y);
        *reinterpret_cast<uint2*>(Ahi + r * RS + c4 * 8) = h2;
        *reinterpret_cast<uint2*>(Ahi + ABUF + r * RS + c4 * 8) = l2;
    }
    asm volatile("cp.async.wait_group 0;");
    __syncthreads();

    // ---- MMA: 8 warps, each 32 rows x 32 cols ----
    const int warp_m = wid & 1;
    const int warp_n = wid >> 1;
    const int j = lane >> 3;
    const int rr = lane & 7;
    const uint32_t sA = smem_u32(Ahi);
    const uint32_t sW = smem_u32(Whi);

    uint32_t aaddr[2];
#pragma unroll
    for (int mt = 0; mt < 2; mt++)
        aaddr[mt] = sA + (uint32_t)((warp_m * 32 + mt * 16 + (j & 1) * 8 + rr) * RS + (j >> 1) * 16);
    uint32_t baddr[2];
#pragma unroll
    for (int p = 0; p < 2; p++)
        baddr[p] = sW + (uint32_t)(((j & 1) * 8 + rr) * RS + (warp_n * 32 + p * 16 + (j >> 1) * 8) * 2);

    float acc[2][4][4];
#pragma unroll
    for (int mt = 0; mt < 2; mt++)
#pragma unroll
        for (int nt = 0; nt < 4; nt++)
#pragma unroll
            for (int q = 0; q < 4; q++) acc[mt][nt][q] = 0.0f;

#pragma unroll
    for (int ks = 0; ks < 8; ks++) {
        uint32_t ah[2][4], al[2][4], bh[2][4], bl[2][4];
#pragma unroll
        for (int mt = 0; mt < 2; mt++) {
            LDSM_X4(ah[mt], aaddr[mt]);
            LDSM_X4(al[mt], aaddr[mt] + ABUF);
            aaddr[mt] += 32;
        }
#pragma unroll
        for (int p = 0; p < 2; p++) {
            LDSM_X4_T(bh[p], baddr[p]);
            LDSM_X4_T(bl[p], baddr[p] + WBUF);
            baddr[p] += 16 * RS;
        }
#pragma unroll
        for (int mt = 0; mt < 2; mt++)
#pragma unroll
            for (int nt = 0; nt < 4; nt++) {
                const int p = nt >> 1, t2 = (nt & 1) * 2;
                MMA_BF16(acc[mt][nt], ah[mt], bh[p][t2], bh[p][t2 + 1]);
                MMA_BF16(acc[mt][nt], ah[mt], bl[p][t2], bl[p][t2 + 1]);
                MMA_BF16(acc[mt][nt], al[mt], bh[p][t2], bh[p][t2 + 1]);
            }
    }

    // ---- epilogue ----
    float* ssum = reinterpret_cast<float*>(smem);    // reuse A region
    if (MODE == 0) {
        __syncthreads();
        if (tid < 256) ssum[tid] = 0.0f;
        __syncthreads();
    }

    float sv[8], qv[8];
#pragma unroll
    for (int i = 0; i < 8; i++) { sv[i] = 0.0f; qv[i] = 0.0f; }

#pragma unroll
    for (int mt = 0; mt < 2; mt++) {
#pragma unroll
        for (int nt = 0; nt < 4; nt++) {
            int row = tile * 64 + warp_m * 32 + mt * 16 + (lane >> 2);
            int col = warp_n * 32 + nt * 8 + (lane & 3) * 2;
            float2 bv = *reinterpret_cast<const float2*>(bias + col);
#pragma unroll
            for (int hh = 0; hh < 2; hh++) {
                int grow = row + hh * 8;
                if (grow < NN) {
                    float2 o;
                    o.x = acc[mt][nt][hh * 2 + 0] + bv.x;
                    o.y = acc[mt][nt][hh * 2 + 1] + bv.y;
                    if (MODE == 0) {
                        sv[nt * 2 + 0] += o.x; qv[nt * 2 + 0] += o.x * o.x;
                        sv[nt * 2 + 1] += o.y; qv[nt * 2 + 1] += o.y * o.y;
                    } else {
                        o.x = relu(o.x); o.y = relu(o.y);
                        if (add_prev) {
                            float2 hp = *reinterpret_cast<const float2*>(
                                h_prev + (size_t)grow * DD + col);
                            o.x += hp.x; o.y += hp.y;
                        }
                    }
                    *reinterpret_cast<float2*>(out + (size_t)grow * DD + col) = o;
                }
            }
        }
    }

    if (MODE == 0) {
#pragma unroll
        for (int i = 0; i < 8; i++) {
#pragma unroll
            for (int k = 4; k < 32; k <<= 1) {
                sv[i] += __shfl_xor_sync(0xffffffff, sv[i], k);
                qv[i] += __shfl_xor_sync(0xffffffff, qv[i], k);
            }
        }
        if (lane < 4) {
#pragma unroll
            for (int i = 0; i < 8; i++) {
                int col = warp_n * 32 + (i >> 1) * 8 + lane * 2 + (i & 1);
                atomicAdd(&ssum[col], sv[i]);
                atomicAdd(&ssum[128 + col], qv[i]);
            }
        }
        __syncthreads();
        if (tid < 128) {
            atomicAdd(&g_sumL[l][tid], ssum[tid]);
            atomicAdd(&g_sumsqL[l][tid], ssum[128 + tid]);
        }
    }
}

// ---------------- launch ---------------------------------------------------
extern "C" void kernel_launch(void* const* d_in, const int* in_sizes, int n_in,
                              void* d_out, int out_size) {
    const float* x     = (const float*)d_in[0];
    const int* ei      = (const int*)d_in[1];
    const float* ea    = (const float*)d_in[2];
    const float* We    = (const float*)d_in[3];
    const float* be    = (const float*)d_in[4];
    const float* eps   = (const float*)d_in[5];
    const float* W1    = (const float*)d_in[6];
    const float* b1    = (const float*)d_in[7];
    const float* gamma = (const float*)d_in[8];
    const float* beta  = (const float*)d_in[9];
    const float* W2    = (const float*)d_in[10];
    const float* b2    = (const float*)d_in[11];
    float* out         = (float*)d_out;

    float *hbuf, *aggbuf, *ybuf;
    cudaGetSymbolAddress((void**)&hbuf, g_h);
    cudaGetSymbolAddress((void**)&aggbuf, g_agg);
    cudaGetSymbolAddress((void**)&ybuf, g_y);

    cudaFuncSetAttribute(gemm_hmma_kernel<0>, cudaFuncAttributeMaxDynamicSharedMemorySize, SMEM_BYTES);
    cudaFuncSetAttribute(gemm_hmma_kernel<1>, cudaFuncAttributeMaxDynamicSharedMemorySize, SMEM_BYTES);

    const int* src = ei;
    const int* dst = ei + NE;
    const int nblk = (NN + 255) / 256;        // 391

    k_zero<<<130, 1024>>>(W1, W2);
    k_hist<<<(NE + 255) / 256, 256>>>(dst);
    k_scan1<<<nblk, 256>>>();
    k_scan2apply<<<nblk, 256>>>();
    k_fill<<<(NE + 255) / 256, 256>>>(src, dst, ea);

    const int aggBlocks = (NN * 32 + 255) / 256;   // 12500

    for (int l = 0; l < NL; l++) {
        const float* h_in = (l == 0) ? x : hbuf;
        float* h_out = (l == NL - 1) ? out : hbuf;

        agg_kernel<<<aggBlocks, 256>>>(h_in, We + l * DD, be + l * DD, eps, l);

        gemm_hmma_kernel<0><<<NT2, 256, SMEM_BYTES>>>(
            aggbuf, l * 2, b1 + l * DD, nullptr, ybuf, 0, l, nullptr, nullptr);

        gemm_hmma_kernel<1><<<NT2, 256, SMEM_BYTES>>>(
            ybuf, l * 2 + 1, b2 + l * DD, hbuf, h_out,
            (l > 0) ? 1 : 0, l, gamma + l * DD, beta + l * DD);
    }
}

// round 12
// speedup vs baseline: 1.8927x; 1.2733x over previous
#include <cuda_runtime.h>
#include <cuda_bf16.h>
#include <cstdint>

#define NN 100000
#define NE 600000
#define DD 128
#define NL 4
#define NT2 1563          // ceil(NN/64)
#define GGRID 304         // persistent GEMM grid: 2 CTA/SM x 152 SM

#define RS 272            // padded row stride bytes (136 bf16)
#define ABUF 17408        // 64*272
#define WBUF 34816        // 128*272
#define WMAT 69632        // hi+lo image per matrix
#define SMEM_BYTES (2 * ABUF + 2 * WBUF)   // 104448

// ---------------- scratch (device globals) ---------------------------------
__device__ float g_h[NN * DD];
__device__ float g_agg[NN * DD];
__device__ float g_y[NN * DD];
__device__ float g_sumL[NL][DD];
__device__ float g_sumsqL[NL][DD];
__device__ int   g_cnt[NN];
__device__ int   g_off[NN + 1];
__device__ int   g_bsum[512];
__device__ int   g_cur[NN];
__device__ uint2 g_edges[NE];     // (src, ea bits) sorted by dst
__device__ unsigned char g_wt[8 * WMAT];   // pre-tiled bf16 hi|lo weight images

__device__ __forceinline__ float relu(float v) { return fmaxf(v, 0.0f); }

__device__ __forceinline__ uint32_t smem_u32(const void* p) {
    uint32_t a;
    asm("{ .reg .u64 t; cvta.to.shared.u64 t, %1; cvt.u32.u64 %0, t; }" : "=r"(a) : "l"(p));
    return a;
}

__device__ __forceinline__ void split2(float x, float y, uint32_t& h, uint32_t& l) {
    __nv_bfloat16 hx = __float2bfloat16_rn(x), hy = __float2bfloat16_rn(y);
    __nv_bfloat16 lx = __float2bfloat16_rn(x - __bfloat162float(hx));
    __nv_bfloat16 ly = __float2bfloat16_rn(y - __bfloat162float(hy));
    __nv_bfloat162 hp = __halves2bfloat162(hx, hy);
    __nv_bfloat162 lp = __halves2bfloat162(lx, ly);
    h = *reinterpret_cast<uint32_t*>(&hp);
    l = *reinterpret_cast<uint32_t*>(&lp);
}

#define LDSM_X4(r, a) \
    asm volatile("ldmatrix.sync.aligned.m8n8.x4.shared.b16 {%0,%1,%2,%3}, [%4];" \
        : "=r"((r)[0]), "=r"((r)[1]), "=r"((r)[2]), "=r"((r)[3]) : "r"(a))

#define LDSM_X4_T(r, a) \
    asm volatile("ldmatrix.sync.aligned.m8n8.x4.trans.shared.b16 {%0,%1,%2,%3}, [%4];" \
        : "=r"((r)[0]), "=r"((r)[1]), "=r"((r)[2]), "=r"((r)[3]) : "r"(a))

#define MMA_BF16(c, a, b0, b1) \
    asm volatile("mma.sync.aligned.m16n8k16.row.col.f32.bf16.bf16.f32 " \
        "{%0,%1,%2,%3},{%4,%5,%6,%7},{%8,%9},{%0,%1,%2,%3};" \
        : "+f"((c)[0]), "+f"((c)[1]), "+f"((c)[2]), "+f"((c)[3]) \
        : "r"((a)[0]), "r"((a)[1]), "r"((a)[2]), "r"((a)[3]), "r"(b0), "r"(b1))

#define CP_ASYNC16(d, s) \
    asm volatile("cp.async.ca.shared.global [%0], [%1], 16;" :: "r"(d), "l"(s))

// =================== preprocessing (5 launches, R8-proven) ==================
__global__ void k_zero(const float* __restrict__ W1, const float* __restrict__ W2) {
    int gid = blockIdx.x * blockDim.x + threadIdx.x;
    if (gid < NN) g_cnt[gid] = 0;
    if (gid < NL * DD) {
        (&g_sumL[0][0])[gid] = 0.0f;
        (&g_sumsqL[0][0])[gid] = 0.0f;
    }
    if (gid < 32768) {               // 8 matrices x 4096 float4
        int m = gid >> 12;
        int rem = gid & 4095;
        int r = rem >> 5, c4 = rem & 31;
        const float* Wsrc = ((m & 1) ? W2 : W1) + (size_t)(m >> 1) * DD * DD;
        float4 v = reinterpret_cast<const float4*>(Wsrc + (size_t)r * DD)[c4];
        uint2 h2, l2;
        split2(v.x, v.y, h2.x, l2.x);
        split2(v.z, v.w, h2.y, l2.y);
        unsigned char* base = g_wt + (size_t)m * WMAT;
        *reinterpret_cast<uint2*>(base + r * RS + c4 * 8) = h2;
        *reinterpret_cast<uint2*>(base + WBUF + r * RS + c4 * 8) = l2;
    }
}
__global__ void k_hist(const int* __restrict__ dst) {
    int e = blockIdx.x * blockDim.x + threadIdx.x;
    if (e < NE) atomicAdd(&g_cnt[dst[e]], 1);
}
__global__ void k_scan1() {
    __shared__ int sh[256];
    int t = threadIdx.x;
    int i = blockIdx.x * 256 + t;
    int v = (i < NN) ? g_cnt[i] : 0;
    sh[t] = v;
    __syncthreads();
    for (int s = 1; s < 256; s <<= 1) {
        int u = (t >= s) ? sh[t - s] : 0;
        __syncthreads();
        sh[t] += u;
        __syncthreads();
    }
    if (i < NN) g_off[i] = sh[t] - v;
    if (t == 255) g_bsum[blockIdx.x] = sh[255];
}
__global__ void k_scan2apply() {     // grid nblk, block 256
    __shared__ int sh[256];
    int b = blockIdx.x, t = threadIdx.x;
    int acc = 0;
    for (int i = t; i < b; i += 256) acc += g_bsum[i];
    sh[t] = acc;
    __syncthreads();
    for (int s = 128; s > 0; s >>= 1) {
        if (t < s) sh[t] += sh[t + s];
        __syncthreads();
    }
    int prefix = sh[0];
    int i = b * 256 + t;
    if (i < NN) { g_off[i] += prefix; g_cur[i] = 0; }
    if (b == 0 && t == 0) g_off[NN] = NE;
}
__global__ void k_fill(const int* __restrict__ src, const int* __restrict__ dst,
                       const float* __restrict__ ea) {
    int e = blockIdx.x * blockDim.x + threadIdx.x;
    if (e >= NE) return;
    int d = dst[e];
    int pos = g_off[d] + atomicAdd(&g_cur[d], 1);
    g_edges[pos] = make_uint2((uint32_t)src[e], __float_as_uint(ea[e]));
}

// =================== aggregation: warp per node, high occupancy =============
__global__ void __launch_bounds__(256) agg_kernel(
        const float* __restrict__ Xin,
        const float* __restrict__ We, const float* __restrict__ be,
        const float* __restrict__ eps, int l) {
    int n = (blockIdx.x * blockDim.x + threadIdx.x) >> 5;
    int lane = threadIdx.x & 31;
    if (n >= NN) return;
    const float4* X4 = reinterpret_cast<const float4*>(Xin);
    float4 w4 = reinterpret_cast<const float4*>(We)[lane];
    float4 b4 = reinterpret_cast<const float4*>(be)[lane];
    float s1 = 1.0f + eps[l];
    float4 hv = X4[(size_t)n * 32 + lane];
    float4 acc;
    acc.x = s1 * hv.x; acc.y = s1 * hv.y;
    acc.z = s1 * hv.z; acc.w = s1 * hv.w;
    int base = g_off[n];
    int deg = g_off[n + 1] - base;
    int i = 0;
    for (; i + 2 <= deg; i += 2) {
        uint2 e0 = g_edges[base + i];
        uint2 e1 = g_edges[base + i + 1];
        float4 h0 = X4[(size_t)e0.x * 32 + lane];
        float4 h1 = X4[(size_t)e1.x * 32 + lane];
        float a0 = __uint_as_float(e0.y);
        float a1 = __uint_as_float(e1.y);
        acc.x += relu(h0.x + fmaf(a0, w4.x, b4.x)) + relu(h1.x + fmaf(a1, w4.x, b4.x));
        acc.y += relu(h0.y + fmaf(a0, w4.y, b4.y)) + relu(h1.y + fmaf(a1, w4.y, b4.y));
        acc.z += relu(h0.z + fmaf(a0, w4.z, b4.z)) + relu(h1.z + fmaf(a1, w4.z, b4.z));
        acc.w += relu(h0.w + fmaf(a0, w4.w, b4.w)) + relu(h1.w + fmaf(a1, w4.w, b4.w));
    }
    if (i < deg) {
        uint2 e0 = g_edges[base + i];
        float4 h0 = X4[(size_t)e0.x * 32 + lane];
        float a0 = __uint_as_float(e0.y);
        acc.x += relu(h0.x + fmaf(a0, w4.x, b4.x));
        acc.y += relu(h0.y + fmaf(a0, w4.y, b4.y));
        acc.z += relu(h0.z + fmaf(a0, w4.z, b4.z));
        acc.w += relu(h0.w + fmaf(a0, w4.w, b4.w));
    }
    reinterpret_cast<float4*>(g_agg)[(size_t)n * 32 + lane] = acc;
}

// =================== persistent HMMA GEMM (304 CTAs, tiles strided) ========
// MODE 0: A = g_agg tile;  y = A@W1+b1; BN stats accumulated in regs -> g_sumL[l]
// MODE 1: A = relu(y*scale+shift); out = relu(A@W2+b2) (+h_prev)
template <int MODE>
__global__ void __launch_bounds__(256, 2) gemm_hmma_kernel(
        const float* __restrict__ Xin,
        int widx,
        const float* __restrict__ bias,
        const float* __restrict__ h_prev,
        float* __restrict__ out,
        int add_prev, int l,
        const float* __restrict__ gamma, const float* __restrict__ beta) {
    extern __shared__ __align__(16) char smem[];
    __shared__ __align__(16) float s_scale[DD];
    __shared__ __align__(16) float s_shift[DD];
    __shared__ __align__(16) float s_stats[256];
    char* Ahi = smem;
    char* Whi = smem + 2 * ABUF;
    const int tid = threadIdx.x;       // 256
    const int wid = tid >> 5;
    const int lane = tid & 31;

    // ---- W copy via cp.async, ONCE per CTA ----
    {
        const unsigned char* wsrc = g_wt + (size_t)widx * WMAT;
        uint32_t wdst = smem_u32(Whi);
#pragma unroll
        for (int i = 0; i < 17; i++) {
            int idx = i * 256 + tid;   // 4352 x 16B
            CP_ASYNC16(wdst + idx * 16, wsrc + idx * 16);
        }
        asm volatile("cp.async.commit_group;");
    }

    if (MODE == 0) {
        s_stats[tid] = 0.0f;
    } else {
        if (tid < DD) {
            float mu = g_sumL[l][tid] * (1.0f / NN);
            float var = g_sumsqL[l][tid] * (1.0f / NN) - mu * mu;
            float rs = rsqrtf(var + 1e-5f);
            float sc = gamma[tid] * rs;
            s_scale[tid] = sc;
            s_shift[tid] = fmaf(-mu, sc, beta[tid]);
        }
    }
    __syncthreads();

    const int warp_m = wid & 1;
    const int warp_n = wid >> 1;
    const int j = lane >> 3;
    const int rr = lane & 7;
    const uint32_t sA = smem_u32(Ahi);
    const uint32_t sW = smem_u32(Whi);

    // per-thread BN stat accumulators (MODE 0), across all tiles
    float sv[8], qv[8];
#pragma unroll
    for (int i = 0; i < 8; i++) { sv[i] = 0.0f; qv[i] = 0.0f; }

    for (int tile = blockIdx.x; tile < NT2; tile += GGRID) {
        // ---- A fill ----
        for (int i = tid; i < 2048; i += 256) {
            int r = i >> 5, c4 = i & 31;
            int grow = tile * 64 + r;
            float4 v = make_float4(0.f, 0.f, 0.f, 0.f);
            if (grow < NN) {
                v = reinterpret_cast<const float4*>(Xin + (size_t)grow * DD)[c4];
                if (MODE == 1) {
                    float4 sc = reinterpret_cast<const float4*>(s_scale)[c4];
                    float4 sh = reinterpret_cast<const float4*>(s_shift)[c4];
                    v.x = relu(fmaf(v.x, sc.x, sh.x));
                    v.y = relu(fmaf(v.y, sc.y, sh.y));
                    v.z = relu(fmaf(v.z, sc.z, sh.z));
                    v.w = relu(fmaf(v.w, sc.w, sh.w));
                }
            }
            uint2 h2, l2;
            split2(v.x, v.y, h2.x, l2.x);
            split2(v.z, v.w, h2.y, l2.y);
            *reinterpret_cast<uint2*>(Ahi + r * RS + c4 * 8) = h2;
            *reinterpret_cast<uint2*>(Ahi + ABUF + r * RS + c4 * 8) = l2;
        }
        asm volatile("cp.async.wait_group 0;");
        __syncthreads();

        // ---- MMA: 8 warps, each 32 rows x 32 cols ----
        uint32_t aaddr[2];
#pragma unroll
        for (int mt = 0; mt < 2; mt++)
            aaddr[mt] = sA + (uint32_t)((warp_m * 32 + mt * 16 + (j & 1) * 8 + rr) * RS + (j >> 1) * 16);
        uint32_t baddr[2];
#pragma unroll
        for (int p = 0; p < 2; p++)
            baddr[p] = sW + (uint32_t)(((j & 1) * 8 + rr) * RS + (warp_n * 32 + p * 16 + (j >> 1) * 8) * 2);

        float acc[2][4][4];
#pragma unroll
        for (int mt = 0; mt < 2; mt++)
#pragma unroll
            for (int nt = 0; nt < 4; nt++)
#pragma unroll
                for (int q = 0; q < 4; q++) acc[mt][nt][q] = 0.0f;

#pragma unroll
        for (int ks = 0; ks < 8; ks++) {
            uint32_t ah[2][4], al[2][4], bh[2][4], bl[2][4];
#pragma unroll
            for (int mt = 0; mt < 2; mt++) {
                LDSM_X4(ah[mt], aaddr[mt]);
                LDSM_X4(al[mt], aaddr[mt] + ABUF);
                aaddr[mt] += 32;
            }
#pragma unroll
            for (int p = 0; p < 2; p++) {
                LDSM_X4_T(bh[p], baddr[p]);
                LDSM_X4_T(bl[p], baddr[p] + WBUF);
                baddr[p] += 16 * RS;
            }
#pragma unroll
            for (int mt = 0; mt < 2; mt++)
#pragma unroll
                for (int nt = 0; nt < 4; nt++) {
                    const int p = nt >> 1, t2 = (nt & 1) * 2;
                    MMA_BF16(acc[mt][nt], ah[mt], bh[p][t2], bh[p][t2 + 1]);
                    MMA_BF16(acc[mt][nt], ah[mt], bl[p][t2], bl[p][t2 + 1]);
                    MMA_BF16(acc[mt][nt], al[mt], bh[p][t2], bh[p][t2 + 1]);
                }
        }

        // ---- epilogue ----
#pragma unroll
        for (int mt = 0; mt < 2; mt++) {
#pragma unroll
            for (int nt = 0; nt < 4; nt++) {
                int row = tile * 64 + warp_m * 32 + mt * 16 + (lane >> 2);
                int col = warp_n * 32 + nt * 8 + (lane & 3) * 2;
                float2 bv = *reinterpret_cast<const float2*>(bias + col);
#pragma unroll
                for (int hh = 0; hh < 2; hh++) {
                    int grow = row + hh * 8;
                    if (grow < NN) {
                        float2 o;
                        o.x = acc[mt][nt][hh * 2 + 0] + bv.x;
                        o.y = acc[mt][nt][hh * 2 + 1] + bv.y;
                        if (MODE == 0) {
                            sv[nt * 2 + 0] += o.x; qv[nt * 2 + 0] += o.x * o.x;
                            sv[nt * 2 + 1] += o.y; qv[nt * 2 + 1] += o.y * o.y;
                        } else {
                            o.x = relu(o.x); o.y = relu(o.y);
                            if (add_prev) {
                                float2 hp = *reinterpret_cast<const float2*>(
                                    h_prev + (size_t)grow * DD + col);
                                o.x += hp.x; o.y += hp.y;
                            }
                        }
                        *reinterpret_cast<float2*>(out + (size_t)grow * DD + col) = o;
                    }
                }
            }
        }
        __syncthreads();    // A region reused next iteration
    }

    // ---- final BN stats flush (MODE 0) ----
    if (MODE == 0) {
#pragma unroll
        for (int i = 0; i < 8; i++) {
#pragma unroll
            for (int k = 4; k < 32; k <<= 1) {
                sv[i] += __shfl_xor_sync(0xffffffff, sv[i], k);
                qv[i] += __shfl_xor_sync(0xffffffff, qv[i], k);
            }
        }
        if (lane < 4) {
#pragma unroll
            for (int i = 0; i < 8; i++) {
                int col = warp_n * 32 + (i >> 1) * 8 + lane * 2 + (i & 1);
                atomicAdd(&s_stats[col], sv[i]);
                atomicAdd(&s_stats[128 + col], qv[i]);
            }
        }
        __syncthreads();
        if (tid < 128) {
            atomicAdd(&g_sumL[l][tid], s_stats[tid]);
            atomicAdd(&g_sumsqL[l][tid], s_stats[128 + tid]);
        }
    }
}

// ---------------- launch ---------------------------------------------------
extern "C" void kernel_launch(void* const* d_in, const int* in_sizes, int n_in,
                              void* d_out, int out_size) {
    const float* x     = (const float*)d_in[0];
    const int* ei      = (const int*)d_in[1];
    const float* ea    = (const float*)d_in[2];
    const float* We    = (const float*)d_in[3];
    const float* be    = (const float*)d_in[4];
    const float* eps   = (const float*)d_in[5];
    const float* W1    = (const float*)d_in[6];
    const float* b1    = (const float*)d_in[7];
    const float* gamma = (const float*)d_in[8];
    const float* beta  = (const float*)d_in[9];
    const float* W2    = (const float*)d_in[10];
    const float* b2    = (const float*)d_in[11];
    float* out         = (float*)d_out;

    float *hbuf, *aggbuf, *ybuf;
    cudaGetSymbolAddress((void**)&hbuf, g_h);
    cudaGetSymbolAddress((void**)&aggbuf, g_agg);
    cudaGetSymbolAddress((void**)&ybuf, g_y);

    cudaFuncSetAttribute(gemm_hmma_kernel<0>, cudaFuncAttributeMaxDynamicSharedMemorySize, SMEM_BYTES);
    cudaFuncSetAttribute(gemm_hmma_kernel<1>, cudaFuncAttributeMaxDynamicSharedMemorySize, SMEM_BYTES);

    const int* src = ei;
    const int* dst = ei + NE;
    const int nblk = (NN + 255) / 256;        // 391

    k_zero<<<130, 1024>>>(W1, W2);
    k_hist<<<(NE + 255) / 256, 256>>>(dst);
    k_scan1<<<nblk, 256>>>();
    k_scan2apply<<<nblk, 256>>>();
    k_fill<<<(NE + 255) / 256, 256>>>(src, dst, ea);

    const int aggBlocks = (NN * 32 + 255) / 256;   // 12500

    for (int l = 0; l < NL; l++) {
        const float* h_in = (l == 0) ? x : hbuf;
        float* h_out = (l == NL - 1) ? out : hbuf;

        agg_kernel<<<aggBlocks, 256>>>(h_in, We + l * DD, be + l * DD, eps, l);

        gemm_hmma_kernel<0><<<GGRID, 256, SMEM_BYTES>>>(
            aggbuf, l * 2, b1 + l * DD, nullptr, ybuf, 0, l, nullptr, nullptr);

        gemm_hmma_kernel<1><<<GGRID, 256, SMEM_BYTES>>>(
            ybuf, l * 2 + 1, b2 + l * DD, hbuf, h_out,
            (l > 0) ? 1 : 0, l, gamma + l * DD, beta + l * DD);
    }
}

// round 13
// speedup vs baseline: 1.9059x; 1.0070x over previous
#include <cuda_runtime.h>
#include <cuda_bf16.h>
#include <cstdint>

#define NN 100000
#define NE 600000
#define DD 128
#define NL 4
#define NT2 1563          // ceil(NN/64)
#define NBLK 391          // ceil(NN/256)
#define GGRID 304         // persistent GEMM grid: 2 CTA/SM x 152 SM

#define RS 272            // padded row stride bytes (136 bf16)
#define ABUF 17408        // 64*272
#define WBUF 34816        // 128*272
#define WMAT 69632        // hi+lo image per matrix
#define ATILE 34816       // hi+lo image per 64-row A tile
#define SMEM_BYTES (2 * ABUF + 2 * WBUF)   // 104448

// ---------------- scratch (device globals) ---------------------------------
__device__ float g_h[NN * DD];
__device__ float g_y[NN * DD];
__device__ float g_sumL[NL][DD];
__device__ float g_sumsqL[NL][DD];
__device__ int   g_cnt[NN];       // invariant: zero at kernel_launch entry
__device__ int   g_off[NN + 1];
__device__ int   g_bsum[512];
__device__ int   g_cur[NN];
__device__ int   g_scanctr;       // invariant: zero at kernel_launch entry
__device__ uint2 g_edges[NE];     // (src, ea bits) sorted by dst
__device__ unsigned char g_wt[8 * WMAT];          // pre-tiled weight images
__device__ uint4 g_atile[(size_t)NT2 * ATILE / 16];  // pre-tiled A images (bf16 hi|lo)

__device__ __forceinline__ float relu(float v) { return fmaxf(v, 0.0f); }

__device__ __forceinline__ uint32_t smem_u32(const void* p) {
    uint32_t a;
    asm("{ .reg .u64 t; cvta.to.shared.u64 t, %1; cvt.u32.u64 %0, t; }" : "=r"(a) : "l"(p));
    return a;
}

__device__ __forceinline__ void split2(float x, float y, uint32_t& h, uint32_t& l) {
    __nv_bfloat16 hx = __float2bfloat16_rn(x), hy = __float2bfloat16_rn(y);
    __nv_bfloat16 lx = __float2bfloat16_rn(x - __bfloat162float(hx));
    __nv_bfloat16 ly = __float2bfloat16_rn(y - __bfloat162float(hy));
    __nv_bfloat162 hp = __halves2bfloat162(hx, hy);
    __nv_bfloat162 lp = __halves2bfloat162(lx, ly);
    h = *reinterpret_cast<uint32_t*>(&hp);
    l = *reinterpret_cast<uint32_t*>(&lp);
}

#define LDSM_X4(r, a) \
    asm volatile("ldmatrix.sync.aligned.m8n8.x4.shared.b16 {%0,%1,%2,%3}, [%4];" \
        : "=r"((r)[0]), "=r"((r)[1]), "=r"((r)[2]), "=r"((r)[3]) : "r"(a))

#define LDSM_X4_T(r, a) \
    asm volatile("ldmatrix.sync.aligned.m8n8.x4.trans.shared.b16 {%0,%1,%2,%3}, [%4];" \
        : "=r"((r)[0]), "=r"((r)[1]), "=r"((r)[2]), "=r"((r)[3]) : "r"(a))

#define MMA_BF16(c, a, b0, b1) \
    asm volatile("mma.sync.aligned.m16n8k16.row.col.f32.bf16.bf16.f32 " \
        "{%0,%1,%2,%3},{%4,%5,%6,%7},{%8,%9},{%0,%1,%2,%3};" \
        : "+f"((c)[0]), "+f"((c)[1]), "+f"((c)[2]), "+f"((c)[3]) \
        : "r"((a)[0]), "r"((a)[1]), "r"((a)[2]), "r"((a)[3]), "r"(b0), "r"(b1))

#define CP_ASYNC16(d, s) \
    asm volatile("cp.async.ca.shared.global [%0], [%1], 16;" :: "r"(d), "l"(s))

// =================== preprocessing (3 launches) =============================
// 1) histogram (g_cnt zero by invariant), zero stats, pre-tile weights
__global__ void k_pre1(const int* __restrict__ dst,
                       const float* __restrict__ W1, const float* __restrict__ W2) {
    int gid = blockIdx.x * blockDim.x + threadIdx.x;
    if (gid < NE) atomicAdd(&g_cnt[dst[gid]], 1);
    if (gid < NL * DD) {
        (&g_sumL[0][0])[gid] = 0.0f;
        (&g_sumsqL[0][0])[gid] = 0.0f;
    }
    if (gid < 32768) {               // 8 matrices x 4096 float4
        int m = gid >> 12;
        int rem = gid & 4095;
        int r = rem >> 5, c4 = rem & 31;
        const float* Wsrc = ((m & 1) ? W2 : W1) + (size_t)(m >> 1) * DD * DD;
        float4 v = reinterpret_cast<const float4*>(Wsrc + (size_t)r * DD)[c4];
        uint2 h2, l2;
        split2(v.x, v.y, h2.x, l2.x);
        split2(v.z, v.w, h2.y, l2.y);
        unsigned char* base = g_wt + (size_t)m * WMAT;
        *reinterpret_cast<uint2*>(base + r * RS + c4 * 8) = h2;
        *reinterpret_cast<uint2*>(base + WBUF + r * RS + c4 * 8) = l2;
    }
}

// 2) single-kernel exclusive scan (all NBLK blocks resident); restores g_cnt=0
__global__ void k_scan() {
    __shared__ int sh[256];
    __shared__ int sh2[256];
    const int b = blockIdx.x, t = threadIdx.x;
    const int i = b * 256 + t;
    int v = (i < NN) ? g_cnt[i] : 0;
    if (i < NN) g_cnt[i] = 0;                    // restore invariant
    sh[t] = v;
    __syncthreads();
    for (int s = 1; s < 256; s <<= 1) {
        int u = (t >= s) ? sh[t - s] : 0;
        __syncthreads();
        sh[t] += u;
        __syncthreads();
    }
    if (t == 255) {
        g_bsum[b] = sh[255];
        __threadfence();
        atomicAdd(&g_scanctr, 1);
    }
    if (t == 0) {
        while (atomicAdd(&g_scanctr, 0) < NBLK) { }
        __threadfence();
    }
    __syncthreads();
    int acc = 0;
    for (int jx = t; jx < b; jx += 256) acc += g_bsum[jx];
    sh2[t] = acc;
    __syncthreads();
    for (int s = 128; s > 0; s >>= 1) {
        if (t < s) sh2[t] += sh2[t + s];
        __syncthreads();
    }
    int prefix = sh2[0];
    if (i < NN) { g_off[i] = prefix + sh[t] - v; g_cur[i] = 0; }
    if (b == 0 && t == 0) g_off[NN] = NE;
}

// 3) fill CSR edge records; reset scan counter for next replay
__global__ void k_fill(const int* __restrict__ src, const int* __restrict__ dst,
                       const float* __restrict__ ea) {
    int e = blockIdx.x * blockDim.x + threadIdx.x;
    if (e == 0) g_scanctr = 0;
    if (e >= NE) return;
    int d = dst[e];
    int pos = g_off[d] + atomicAdd(&g_cur[d], 1);
    g_edges[pos] = make_uint2((uint32_t)src[e], __float_as_uint(ea[e]));
}

// =================== aggregation: warp per node -> bf16 tile images =========
// writes hi/lo split of (1+eps)*h[n] + sum relu(h[src]+ea*We+be) straight into
// the padded RS-layout tile image consumed by gemm0's cp.async fill.
__global__ void __launch_bounds__(256) agg_kernel(
        const float* __restrict__ Xin,
        const float* __restrict__ We, const float* __restrict__ be,
        const float* __restrict__ eps, int l) {
    int n = (blockIdx.x * blockDim.x + threadIdx.x) >> 5;
    int lane = threadIdx.x & 31;
    if (n >= NN) return;
    const float4* X4 = reinterpret_cast<const float4*>(Xin);
    float4 w4 = reinterpret_cast<const float4*>(We)[lane];
    float4 b4 = reinterpret_cast<const float4*>(be)[lane];
    float s1 = 1.0f + eps[l];
    float4 hv = X4[(size_t)n * 32 + lane];
    float4 acc;
    acc.x = s1 * hv.x; acc.y = s1 * hv.y;
    acc.z = s1 * hv.z; acc.w = s1 * hv.w;
    int base = g_off[n];
    int deg = g_off[n + 1] - base;
    int i = 0;
    for (; i + 2 <= deg; i += 2) {
        uint2 e0 = g_edges[base + i];
        uint2 e1 = g_edges[base + i + 1];
        float4 h0 = X4[(size_t)e0.x * 32 + lane];
        float4 h1 = X4[(size_t)e1.x * 32 + lane];
        float a0 = __uint_as_float(e0.y);
        float a1 = __uint_as_float(e1.y);
        acc.x += relu(h0.x + fmaf(a0, w4.x, b4.x)) + relu(h1.x + fmaf(a1, w4.x, b4.x));
        acc.y += relu(h0.y + fmaf(a0, w4.y, b4.y)) + relu(h1.y + fmaf(a1, w4.y, b4.y));
        acc.z += relu(h0.z + fmaf(a0, w4.z, b4.z)) + relu(h1.z + fmaf(a1, w4.z, b4.z));
        acc.w += relu(h0.w + fmaf(a0, w4.w, b4.w)) + relu(h1.w + fmaf(a1, w4.w, b4.w));
    }
    if (i < deg) {
        uint2 e0 = g_edges[base + i];
        float4 h0 = X4[(size_t)e0.x * 32 + lane];
        float a0 = __uint_as_float(e0.y);
        acc.x += relu(h0.x + fmaf(a0, w4.x, b4.x));
        acc.y += relu(h0.y + fmaf(a0, w4.y, b4.y));
        acc.z += relu(h0.z + fmaf(a0, w4.z, b4.z));
        acc.w += relu(h0.w + fmaf(a0, w4.w, b4.w));
    }
    uint2 h2, l2;
    split2(acc.x, acc.y, h2.x, l2.x);
    split2(acc.z, acc.w, h2.y, l2.y);
    unsigned char* tbase = reinterpret_cast<unsigned char*>(g_atile)
                         + (size_t)(n >> 6) * ATILE + (n & 63) * RS + lane * 8;
    *reinterpret_cast<uint2*>(tbase) = h2;
    *reinterpret_cast<uint2*>(tbase + ABUF) = l2;
}

// =================== persistent HMMA GEMM (304 CTAs) ========================
// MODE 0: A tiles pre-split in g_atile (cp.async); y = A@W1+b1; stats->g_sumL[l]
// MODE 1: A = relu(y*scale+shift); out = relu(A@W2+b2) (+h_prev)
template <int MODE>
__global__ void __launch_bounds__(256, 2) gemm_hmma_kernel(
        const float* __restrict__ Xin,
        int widx,
        const float* __restrict__ bias,
        const float* __restrict__ h_prev,
        float* __restrict__ out,
        int add_prev, int l,
        const float* __restrict__ gamma, const float* __restrict__ beta) {
    extern __shared__ __align__(16) char smem[];
    __shared__ __align__(16) float s_scale[DD];
    __shared__ __align__(16) float s_shift[DD];
    __shared__ __align__(16) float s_stats[256];
    char* Ahi = smem;
    char* Whi = smem + 2 * ABUF;
    const int tid = threadIdx.x;       // 256
    const int wid = tid >> 5;
    const int lane = tid & 31;

    // ---- W copy via cp.async, ONCE per CTA ----
    {
        const unsigned char* wsrc = g_wt + (size_t)widx * WMAT;
        uint32_t wdst = smem_u32(Whi);
#pragma unroll
        for (int i = 0; i < 17; i++) {
            int idx = i * 256 + tid;   // 4352 x 16B
            CP_ASYNC16(wdst + idx * 16, wsrc + idx * 16);
        }
        asm volatile("cp.async.commit_group;");
    }

    if (MODE == 0) {
        s_stats[tid] = 0.0f;
    } else {
        if (tid < DD) {
            float mu = g_sumL[l][tid] * (1.0f / NN);
            float var = g_sumsqL[l][tid] * (1.0f / NN) - mu * mu;
            float rs = rsqrtf(var + 1e-5f);
            float sc = gamma[tid] * rs;
            s_scale[tid] = sc;
            s_shift[tid] = fmaf(-mu, sc, beta[tid]);
        }
    }
    __syncthreads();

    const int warp_m = wid & 1;
    const int warp_n = wid >> 1;
    const int j = lane >> 3;
    const int rr = lane & 7;
    const uint32_t sA = smem_u32(Ahi);
    const uint32_t sW = smem_u32(Whi);

    float sv[8], qv[8];
#pragma unroll
    for (int i = 0; i < 8; i++) { sv[i] = 0.0f; qv[i] = 0.0f; }

    for (int tile = blockIdx.x; tile < NT2; tile += GGRID) {
        // ---- A fill ----
        if (MODE == 0) {
            const unsigned char* asrc = reinterpret_cast<const unsigned char*>(g_atile)
                                      + (size_t)tile * ATILE;
#pragma unroll
            for (int i = 0; i < 9; i++) {
                int idx = i * 256 + tid;    // 2176 x 16B
                if (idx < 2176) CP_ASYNC16(sA + idx * 16, asrc + idx * 16);
            }
            asm volatile("cp.async.commit_group;");
        } else {
            for (int i = tid; i < 2048; i += 256) {
                int r = i >> 5, c4 = i & 31;
                int grow = tile * 64 + r;
                float4 v = make_float4(0.f, 0.f, 0.f, 0.f);
                if (grow < NN) {
                    v = reinterpret_cast<const float4*>(Xin + (size_t)grow * DD)[c4];
                    float4 sc = reinterpret_cast<const float4*>(s_scale)[c4];
                    float4 sh = reinterpret_cast<const float4*>(s_shift)[c4];
                    v.x = relu(fmaf(v.x, sc.x, sh.x));
                    v.y = relu(fmaf(v.y, sc.y, sh.y));
                    v.z = relu(fmaf(v.z, sc.z, sh.z));
                    v.w = relu(fmaf(v.w, sc.w, sh.w));
                }
                uint2 h2, l2;
                split2(v.x, v.y, h2.x, l2.x);
                split2(v.z, v.w, h2.y, l2.y);
                *reinterpret_cast<uint2*>(Ahi + r * RS + c4 * 8) = h2;
                *reinterpret_cast<uint2*>(Ahi + ABUF + r * RS + c4 * 8) = l2;
            }
        }
        asm volatile("cp.async.wait_group 0;");
        __syncthreads();

        // ---- MMA: 8 warps, each 32 rows x 32 cols ----
        uint32_t aaddr[2];
#pragma unroll
        for (int mt = 0; mt < 2; mt++)
            aaddr[mt] = sA + (uint32_t)((warp_m * 32 + mt * 16 + (j & 1) * 8 + rr) * RS + (j >> 1) * 16);
        uint32_t baddr[2];
#pragma unroll
        for (int p = 0; p < 2; p++)
            baddr[p] = sW + (uint32_t)(((j & 1) * 8 + rr) * RS + (warp_n * 32 + p * 16 + (j >> 1) * 8) * 2);

        float acc[2][4][4];
#pragma unroll
        for (int mt = 0; mt < 2; mt++)
#pragma unroll
            for (int nt = 0; nt < 4; nt++)
#pragma unroll
                for (int q = 0; q < 4; q++) acc[mt][nt][q] = 0.0f;

#pragma unroll
        for (int ks = 0; ks < 8; ks++) {
            uint32_t ah[2][4], al[2][4], bh[2][4], bl[2][4];
#pragma unroll
            for (int mt = 0; mt < 2; mt++) {
                LDSM_X4(ah[mt], aaddr[mt]);
                LDSM_X4(al[mt], aaddr[mt] + ABUF);
                aaddr[mt] += 32;
            }
#pragma unroll
            for (int p = 0; p < 2; p++) {
                LDSM_X4_T(bh[p], baddr[p]);
                LDSM_X4_T(bl[p], baddr[p] + WBUF);
                baddr[p] += 16 * RS;
            }
#pragma unroll
            for (int mt = 0; mt < 2; mt++)
#pragma unroll
                for (int nt = 0; nt < 4; nt++) {
                    const int p = nt >> 1, t2 = (nt & 1) * 2;
                    MMA_BF16(acc[mt][nt], ah[mt], bh[p][t2], bh[p][t2 + 1]);
                    MMA_BF16(acc[mt][nt], ah[mt], bl[p][t2], bl[p][t2 + 1]);
                    MMA_BF16(acc[mt][nt], al[mt], bh[p][t2], bh[p][t2 + 1]);
                }
        }

        // ---- epilogue ----
#pragma unroll
        for (int mt = 0; mt < 2; mt++) {
#pragma unroll
            for (int nt = 0; nt < 4; nt++) {
                int row = tile * 64 + warp_m * 32 + mt * 16 + (lane >> 2);
                int col = warp_n * 32 + nt * 8 + (lane & 3) * 2;
                float2 bv = *reinterpret_cast<const float2*>(bias + col);
#pragma unroll
                for (int hh = 0; hh < 2; hh++) {
                    int grow = row + hh * 8;
                    if (grow < NN) {
                        float2 o;
                        o.x = acc[mt][nt][hh * 2 + 0] + bv.x;
                        o.y = acc[mt][nt][hh * 2 + 1] + bv.y;
                        if (MODE == 0) {
                            sv[nt * 2 + 0] += o.x; qv[nt * 2 + 0] += o.x * o.x;
                            sv[nt * 2 + 1] += o.y; qv[nt * 2 + 1] += o.y * o.y;
                        } else {
                            o.x = relu(o.x); o.y = relu(o.y);
                            if (add_prev) {
                                float2 hp = *reinterpret_cast<const float2*>(
                                    h_prev + (size_t)grow * DD + col);
                                o.x += hp.x; o.y += hp.y;
                            }
                        }
                        *reinterpret_cast<float2*>(out + (size_t)grow * DD + col) = o;
                    }
                }
            }
        }
        __syncthreads();    // A region reused next iteration
    }

    // ---- final BN stats flush (MODE 0) ----
    if (MODE == 0) {
#pragma unroll
        for (int i = 0; i < 8; i++) {
#pragma unroll
            for (int k = 4; k < 32; k <<= 1) {
                sv[i] += __shfl_xor_sync(0xffffffff, sv[i], k);
                qv[i] += __shfl_xor_sync(0xffffffff, qv[i], k);
            }
        }
        if (lane < 4) {
#pragma unroll
            for (int i = 0; i < 8; i++) {
                int col = warp_n * 32 + (i >> 1) * 8 + lane * 2 + (i & 1);
                atomicAdd(&s_stats[col], sv[i]);
                atomicAdd(&s_stats[128 + col], qv[i]);
            }
        }
        __syncthreads();
        if (tid < 128) {
            atomicAdd(&g_sumL[l][tid], s_stats[tid]);
            atomicAdd(&g_sumsqL[l][tid], s_stats[128 + tid]);
        }
    }
}

// ---------------- launch ---------------------------------------------------
extern "C" void kernel_launch(void* const* d_in, const int* in_sizes, int n_in,
                              void* d_out, int out_size) {
    const float* x     = (const float*)d_in[0];
    const int* ei      = (const int*)d_in[1];
    const float* ea    = (const float*)d_in[2];
    const float* We    = (const float*)d_in[3];
    const float* be    = (const float*)d_in[4];
    const float* eps   = (const float*)d_in[5];
    const float* W1    = (const float*)d_in[6];
    const float* b1    = (const float*)d_in[7];
    const float* gamma = (const float*)d_in[8];
    const float* beta  = (const float*)d_in[9];
    const float* W2    = (const float*)d_in[10];
    const float* b2    = (const float*)d_in[11];
    float* out         = (float*)d_out;

    float *hbuf, *ybuf;
    cudaGetSymbolAddress((void**)&hbuf, g_h);
    cudaGetSymbolAddress((void**)&ybuf, g_y);

    cudaFuncSetAttribute(gemm_hmma_kernel<0>, cudaFuncAttributeMaxDynamicSharedMemorySize, SMEM_BYTES);
    cudaFuncSetAttribute(gemm_hmma_kernel<1>, cudaFuncAttributeMaxDynamicSharedMemorySize, SMEM_BYTES);

    const int* src = ei;
    const int* dst = ei + NE;

    k_pre1<<<(NE + 255) / 256, 256>>>(dst, W1, W2);
    k_scan<<<NBLK, 256>>>();
    k_fill<<<(NE + 255) / 256, 256>>>(src, dst, ea);

    const int aggBlocks = (NN * 32 + 255) / 256;   // 12500

    for (int l = 0; l < NL; l++) {
        const float* h_in = (l == 0) ? x : hbuf;
        float* h_out = (l == NL - 1) ? out : hbuf;

        agg_kernel<<<aggBlocks, 256>>>(h_in, We + l * DD, be + l * DD, eps, l);

        gemm_hmma_kernel<0><<<GGRID, 256, SMEM_BYTES>>>(
            nullptr, l * 2, b1 + l * DD, nullptr, ybuf, 0, l, nullptr, nullptr);

        gemm_hmma_kernel<1><<<GGRID, 256, SMEM_BYTES>>>(
            ybuf, l * 2 + 1, b2 + l * DD, hbuf, h_out,
            (l > 0) ? 1 : 0, l, gamma + l * DD, beta + l * DD);
    }
}

// round 15
// speedup vs baseline: 1.9271x; 1.0111x over previous
#include <cuda_runtime.h>
#include <cuda_bf16.h>
#include <cstdint>

#define NN 100000
#define NE 600000
#define DD 128
#define NL 4
#define NT2 1563          // ceil(NN/64)
#define NBLK 391          // ceil(NN/256)
#define GGRID 304         // persistent GEMM grid: 2 CTA/SM x 152 SM

#define RS 272            // padded row stride bytes (136 bf16)
#define ABUF 17408        // 64*272
#define WBUF 34816        // 128*272
#define WMAT 69632        // hi+lo image per matrix
#define ATILE 34816       // hi+lo image per 64-row A tile
#define SMEM_BYTES (2 * ABUF + 2 * WBUF)   // 104448

// ---------------- scratch (device globals) ---------------------------------
__device__ float g_h[NN * DD];
__device__ float g_y[NN * DD];
__device__ float g_sumL[NL][DD];
__device__ float g_sumsqL[NL][DD];
__device__ int   g_cnt[NN];       // invariant: zero at kernel_launch entry
__device__ int   g_off[NN + 1];
__device__ int   g_bsum[512];
__device__ int   g_cur[NN];
__device__ int   g_scanctr;       // invariant: zero at kernel_launch entry
__device__ uint2 g_edges[NE];     // (src, ea bits) sorted by dst
__device__ unsigned char g_wt[8 * WMAT];          // pre-tiled weight images
__device__ uint4 g_atile[(size_t)NT2 * ATILE / 16];  // pre-tiled A images (bf16 hi|lo)

__device__ __forceinline__ float relu(float v) { return fmaxf(v, 0.0f); }

__device__ __forceinline__ uint32_t smem_u32(const void* p) {
    uint32_t a;
    asm("{ .reg .u64 t; cvta.to.shared.u64 t, %1; cvt.u32.u64 %0, t; }" : "=r"(a) : "l"(p));
    return a;
}

__device__ __forceinline__ void split2(float x, float y, uint32_t& h, uint32_t& l) {
    __nv_bfloat16 hx = __float2bfloat16_rn(x), hy = __float2bfloat16_rn(y);
    __nv_bfloat16 lx = __float2bfloat16_rn(x - __bfloat162float(hx));
    __nv_bfloat16 ly = __float2bfloat16_rn(y - __bfloat162float(hy));
    __nv_bfloat162 hp = __halves2bfloat162(hx, hy);
    __nv_bfloat162 lp = __halves2bfloat162(lx, ly);
    h = *reinterpret_cast<uint32_t*>(&hp);
    l = *reinterpret_cast<uint32_t*>(&lp);
}

#define LDSM_X4(r, a) \
    asm volatile("ldmatrix.sync.aligned.m8n8.x4.shared.b16 {%0,%1,%2,%3}, [%4];" \
        : "=r"((r)[0]), "=r"((r)[1]), "=r"((r)[2]), "=r"((r)[3]) : "r"(a))

#define LDSM_X4_T(r, a) \
    asm volatile("ldmatrix.sync.aligned.m8n8.x4.trans.shared.b16 {%0,%1,%2,%3}, [%4];" \
        : "=r"((r)[0]), "=r"((r)[1]), "=r"((r)[2]), "=r"((r)[3]) : "r"(a))

#define MMA_BF16(c, a, b0, b1) \
    asm volatile("mma.sync.aligned.m16n8k16.row.col.f32.bf16.bf16.f32 " \
        "{%0,%1,%2,%3},{%4,%5,%6,%7},{%8,%9},{%0,%1,%2,%3};" \
        : "+f"((c)[0]), "+f"((c)[1]), "+f"((c)[2]), "+f"((c)[3]) \
        : "r"((a)[0]), "r"((a)[1]), "r"((a)[2]), "r"((a)[3]), "r"(b0), "r"(b1))

#define CP_ASYNC16(d, s) \
    asm volatile("cp.async.ca.shared.global [%0], [%1], 16;" :: "r"(d), "l"(s))

// =================== preprocessing (3 launches) =============================
__global__ void k_pre1(const int* __restrict__ dst,
                       const float* __restrict__ W1, const float* __restrict__ W2) {
    int gid = blockIdx.x * blockDim.x + threadIdx.x;
    if (gid < NE) atomicAdd(&g_cnt[dst[gid]], 1);
    if (gid < NL * DD) {
        (&g_sumL[0][0])[gid] = 0.0f;
        (&g_sumsqL[0][0])[gid] = 0.0f;
    }
    if (gid < 32768) {               // 8 matrices x 4096 float4
        int m = gid >> 12;
        int rem = gid & 4095;
        int r = rem >> 5, c4 = rem & 31;
        const float* Wsrc = ((m & 1) ? W2 : W1) + (size_t)(m >> 1) * DD * DD;
        float4 v = reinterpret_cast<const float4*>(Wsrc + (size_t)r * DD)[c4];
        uint2 h2, l2;
        split2(v.x, v.y, h2.x, l2.x);
        split2(v.z, v.w, h2.y, l2.y);
        unsigned char* base = g_wt + (size_t)m * WMAT;
        *reinterpret_cast<uint2*>(base + r * RS + c4 * 8) = h2;
        *reinterpret_cast<uint2*>(base + WBUF + r * RS + c4 * 8) = l2;
    }
}

// single-kernel exclusive scan (all NBLK blocks resident); restores g_cnt=0
__global__ void k_scan() {
    __shared__ int sh[256];
    __shared__ int sh2[256];
    const int b = blockIdx.x, t = threadIdx.x;
    const int i = b * 256 + t;
    int v = (i < NN) ? g_cnt[i] : 0;
    if (i < NN) g_cnt[i] = 0;                    // restore invariant
    sh[t] = v;
    __syncthreads();
    for (int s = 1; s < 256; s <<= 1) {
        int u = (t >= s) ? sh[t - s] : 0;
        __syncthreads();
        sh[t] += u;
        __syncthreads();
    }
    if (t == 255) {
        g_bsum[b] = sh[255];
        __threadfence();
        atomicAdd(&g_scanctr, 1);
    }
    if (t == 0) {
        while (atomicAdd(&g_scanctr, 0) < NBLK) { }
        __threadfence();
    }
    __syncthreads();
    int acc = 0;
    for (int jx = t; jx < b; jx += 256) acc += g_bsum[jx];
    sh2[t] = acc;
    __syncthreads();
    for (int s = 128; s > 0; s >>= 1) {
        if (t < s) sh2[t] += sh2[t + s];
        __syncthreads();
    }
    int prefix = sh2[0];
    if (i < NN) { g_off[i] = prefix + sh[t] - v; g_cur[i] = 0; }
    if (b == 0 && t == 0) g_off[NN] = NE;
}

// fill CSR edge records; reset scan counter for next replay
__global__ void k_fill(const int* __restrict__ src, const int* __restrict__ dst,
                       const float* __restrict__ ea) {
    int e = blockIdx.x * blockDim.x + threadIdx.x;
    if (e == 0) g_scanctr = 0;
    if (e >= NE) return;
    int d = dst[e];
    int pos = g_off[d] + atomicAdd(&g_cur[d], 1);
    g_edges[pos] = make_uint2((uint32_t)src[e], __float_as_uint(ea[e]));
}

// =================== aggregation: warp per node, 4-deep gather ==============
__global__ void __launch_bounds__(256) agg_kernel(
        const float* __restrict__ Xin,
        const float* __restrict__ We, const float* __restrict__ be,
        const float* __restrict__ eps, int l) {
    int n = (blockIdx.x * blockDim.x + threadIdx.x) >> 5;
    int lane = threadIdx.x & 31;
    if (n >= NN) return;
    const float4* X4 = reinterpret_cast<const float4*>(Xin);
    float4 w4 = reinterpret_cast<const float4*>(We)[lane];
    float4 b4 = reinterpret_cast<const float4*>(be)[lane];
    float s1 = 1.0f + eps[l];
    float4 hv = X4[(size_t)n * 32 + lane];
    float4 acc;
    acc.x = s1 * hv.x; acc.y = s1 * hv.y;
    acc.z = s1 * hv.z; acc.w = s1 * hv.w;
    int base = g_off[n];
    int deg = g_off[n + 1] - base;
    int i = 0;
    for (; i + 4 <= deg; i += 4) {
        uint2 e0 = g_edges[base + i];
        uint2 e1 = g_edges[base + i + 1];
        uint2 e2 = g_edges[base + i + 2];
        uint2 e3 = g_edges[base + i + 3];
        float4 h0 = X4[(size_t)e0.x * 32 + lane];
        float4 h1 = X4[(size_t)e1.x * 32 + lane];
        float4 h2 = X4[(size_t)e2.x * 32 + lane];
        float4 h3 = X4[(size_t)e3.x * 32 + lane];
        float a0 = __uint_as_float(e0.y);
        float a1 = __uint_as_float(e1.y);
        float a2 = __uint_as_float(e2.y);
        float a3 = __uint_as_float(e3.y);
        acc.x += relu(h0.x + fmaf(a0, w4.x, b4.x)) + relu(h1.x + fmaf(a1, w4.x, b4.x))
               + relu(h2.x + fmaf(a2, w4.x, b4.x)) + relu(h3.x + fmaf(a3, w4.x, b4.x));
        acc.y += relu(h0.y + fmaf(a0, w4.y, b4.y)) + relu(h1.y + fmaf(a1, w4.y, b4.y))
               + relu(h2.y + fmaf(a2, w4.y, b4.y)) + relu(h3.y + fmaf(a3, w4.y, b4.y));
        acc.z += relu(h0.z + fmaf(a0, w4.z, b4.z)) + relu(h1.z + fmaf(a1, w4.z, b4.z))
               + relu(h2.z + fmaf(a2, w4.z, b4.z)) + relu(h3.z + fmaf(a3, w4.z, b4.z));
        acc.w += relu(h0.w + fmaf(a0, w4.w, b4.w)) + relu(h1.w + fmaf(a1, w4.w, b4.w))
               + relu(h2.w + fmaf(a2, w4.w, b4.w)) + relu(h3.w + fmaf(a3, w4.w, b4.w));
    }
    for (; i < deg; i++) {
        uint2 e0 = g_edges[base + i];
        float4 h0 = X4[(size_t)e0.x * 32 + lane];
        float a0 = __uint_as_float(e0.y);
        acc.x += relu(h0.x + fmaf(a0, w4.x, b4.x));
        acc.y += relu(h0.y + fmaf(a0, w4.y, b4.y));
        acc.z += relu(h0.z + fmaf(a0, w4.z, b4.z));
        acc.w += relu(h0.w + fmaf(a0, w4.w, b4.w));
    }
    uint2 h2o, l2o;
    split2(acc.x, acc.y, h2o.x, l2o.x);
    split2(acc.z, acc.w, h2o.y, l2o.y);
    unsigned char* tbase = reinterpret_cast<unsigned char*>(g_atile)
                         + (size_t)(n >> 6) * ATILE + (n & 63) * RS + lane * 8;
    *reinterpret_cast<uint2*>(tbase) = h2o;
    *reinterpret_cast<uint2*>(tbase + ABUF) = l2o;
}

// =================== persistent HMMA GEMM (304 CTAs) ========================
// MODE 0: A tiles pre-split in g_atile (cp.async); y = A@W1+b1; stats->g_sumL[l]
// MODE 1: A = relu(y*scale+shift); out = relu(A@W2+b2) (+h_prev)
template <int MODE>
__global__ void __launch_bounds__(256, 2) gemm_hmma_kernel(
        const float* __restrict__ Xin,
        int widx,
        const float* __restrict__ bias,
        const float* __restrict__ h_prev,
        float* __restrict__ out,
        int add_prev, int l,
        const float* __restrict__ gamma, const float* __restrict__ beta) {
    extern __shared__ __align__(16) char smem[];
    __shared__ __align__(16) float s_scale[DD];
    __shared__ __align__(16) float s_shift[DD];
    __shared__ __align__(16) float s_stats[256];
    char* Ahi = smem;
    char* Whi = smem + 2 * ABUF;
    const int tid = threadIdx.x;       // 256
    const int wid = tid >> 5;
    const int lane = tid & 31;

    // ---- W copy via cp.async, ONCE per CTA ----
    {
        const unsigned char* wsrc = g_wt + (size_t)widx * WMAT;
        uint32_t wdst = smem_u32(Whi);
#pragma unroll
        for (int i = 0; i < 17; i++) {
            int idx = i * 256 + tid;   // 4352 x 16B
            CP_ASYNC16(wdst + idx * 16, wsrc + idx * 16);
        }
        asm volatile("cp.async.commit_group;");
    }

    if (MODE == 0) {
        s_stats[tid] = 0.0f;
    } else {
        if (tid < DD) {
            float mu = g_sumL[l][tid] * (1.0f / NN);
            float var = g_sumsqL[l][tid] * (1.0f / NN) - mu * mu;
            float rs = rsqrtf(var + 1e-5f);
            float sc = gamma[tid] * rs;
            s_scale[tid] = sc;
            s_shift[tid] = fmaf(-mu, sc, beta[tid]);
        }
    }
    __syncthreads();

    const int warp_m = wid & 1;
    const int warp_n = wid >> 1;
    const int j = lane >> 3;
    const int rr = lane & 7;
    const uint32_t sA = smem_u32(Ahi);
    const uint32_t sW = smem_u32(Whi);

    float sv[8], qv[8];
#pragma unroll
    for (int i = 0; i < 8; i++) { sv[i] = 0.0f; qv[i] = 0.0f; }

    for (int tile = blockIdx.x; tile < NT2; tile += GGRID) {
        // ---- A fill ----
        if (MODE == 0) {
            const unsigned char* asrc = reinterpret_cast<const unsigned char*>(g_atile)
                                      + (size_t)tile * ATILE;
#pragma unroll
            for (int i = 0; i < 9; i++) {
                int idx = i * 256 + tid;    // 2176 x 16B
                if (idx < 2176) CP_ASYNC16(sA + idx * 16, asrc + idx * 16);
            }
            asm volatile("cp.async.commit_group;");
        } else {
            for (int i = tid; i < 2048; i += 256) {
                int r = i >> 5, c4 = i & 31;
                int grow = tile * 64 + r;
                float4 v = make_float4(0.f, 0.f, 0.f, 0.f);
                if (grow < NN) {
                    v = reinterpret_cast<const float4*>(Xin + (size_t)grow * DD)[c4];
                    float4 sc = reinterpret_cast<const float4*>(s_scale)[c4];
                    float4 sh = reinterpret_cast<const float4*>(s_shift)[c4];
                    v.x = relu(fmaf(v.x, sc.x, sh.x));
                    v.y = relu(fmaf(v.y, sc.y, sh.y));
                    v.z = relu(fmaf(v.z, sc.z, sh.z));
                    v.w = relu(fmaf(v.w, sc.w, sh.w));
                }
                uint2 h2, l2;
                split2(v.x, v.y, h2.x, l2.x);
                split2(v.z, v.w, h2.y, l2.y);
                *reinterpret_cast<uint2*>(Ahi + r * RS + c4 * 8) = h2;
                *reinterpret_cast<uint2*>(Ahi + ABUF + r * RS + c4 * 8) = l2;
            }
        }
        asm volatile("cp.async.wait_group 0;");
        __syncthreads();

        // ---- MMA: 8 warps, each 32 rows x 32 cols ----
        uint32_t aaddr[2];
#pragma unroll
        for (int mt = 0; mt < 2; mt++)
            aaddr[mt] = sA + (uint32_t)((warp_m * 32 + mt * 16 + (j & 1) * 8 + rr) * RS + (j >> 1) * 16);
        uint32_t baddr[2];
#pragma unroll
        for (int p = 0; p < 2; p++)
            baddr[p] = sW + (uint32_t)(((j & 1) * 8 + rr) * RS + (warp_n * 32 + p * 16 + (j >> 1) * 8) * 2);

        float acc[2][4][4];
#pragma unroll
        for (int mt = 0; mt < 2; mt++)
#pragma unroll
            for (int nt = 0; nt < 4; nt++)
#pragma unroll
                for (int q = 0; q < 4; q++) acc[mt][nt][q] = 0.0f;

#pragma unroll
        for (int ks = 0; ks < 8; ks++) {
            uint32_t ah[2][4], al[2][4], bh[2][4], bl[2][4];
#pragma unroll
            for (int mt = 0; mt < 2; mt++) {
                LDSM_X4(ah[mt], aaddr[mt]);
                LDSM_X4(al[mt], aaddr[mt] + ABUF);
                aaddr[mt] += 32;
            }
#pragma unroll
            for (int p = 0; p < 2; p++) {
                LDSM_X4_T(bh[p], baddr[p]);
                LDSM_X4_T(bl[p], baddr[p] + WBUF);
                baddr[p] += 16 * RS;
            }
#pragma unroll
            for (int mt = 0; mt < 2; mt++)
#pragma unroll
                for (int nt = 0; nt < 4; nt++) {
                    const int p = nt >> 1, t2 = (nt & 1) * 2;
                    MMA_BF16(acc[mt][nt], ah[mt], bh[p][t2], bh[p][t2 + 1]);
                    MMA_BF16(acc[mt][nt], ah[mt], bl[p][t2], bl[p][t2 + 1]);
                    MMA_BF16(acc[mt][nt], al[mt], bh[p][t2], bh[p][t2 + 1]);
                }
        }

        // ---- epilogue ----
#pragma unroll
        for (int mt = 0; mt < 2; mt++) {
#pragma unroll
            for (int nt = 0; nt < 4; nt++) {
                int row = tile * 64 + warp_m * 32 + mt * 16 + (lane >> 2);
                int col = warp_n * 32 + nt * 8 + (lane & 3) * 2;
                float2 bv = *reinterpret_cast<const float2*>(bias + col);
#pragma unroll
                for (int hh = 0; hh < 2; hh++) {
                    int grow = row + hh * 8;
                    if (grow < NN) {
                        float2 o;
                        o.x = acc[mt][nt][hh * 2 + 0] + bv.x;
                        o.y = acc[mt][nt][hh * 2 + 1] + bv.y;
                        if (MODE == 0) {
                            sv[nt * 2 + 0] += o.x; qv[nt * 2 + 0] += o.x * o.x;
                            sv[nt * 2 + 1] += o.y; qv[nt * 2 + 1] += o.y * o.y;
                        } else {
                            o.x = relu(o.x); o.y = relu(o.y);
                            if (add_prev) {
                                float2 hp = *reinterpret_cast<const float2*>(
                                    h_prev + (size_t)grow * DD + col);
                                o.x += hp.x; o.y += hp.y;
                            }
                        }
                        *reinterpret_cast<float2*>(out + (size_t)grow * DD + col) = o;
                    }
                }
            }
        }
        __syncthreads();    // A region reused next iteration
    }

    // ---- final BN stats flush (MODE 0) ----
    if (MODE == 0) {
#pragma unroll
        for (int i = 0; i < 8; i++) {
#pragma unroll
            for (int k = 4; k < 32; k <<= 1) {
                sv[i] += __shfl_xor_sync(0xffffffff, sv[i], k);
                qv[i] += __shfl_xor_sync(0xffffffff, qv[i], k);
            }
        }
        if (lane < 4) {
#pragma unroll
            for (int i = 0; i < 8; i++) {
                int col = warp_n * 32 + (i >> 1) * 8 + lane * 2 + (i & 1);
                atomicAdd(&s_stats[col], sv[i]);
                atomicAdd(&s_stats[128 + col], qv[i]);
            }
        }
        __syncthreads();
        if (tid < 128) {
            atomicAdd(&g_sumL[l][tid], s_stats[tid]);
            atomicAdd(&g_sumsqL[l][tid], s_stats[128 + tid]);
        }
    }
}

// ---------------- launch ---------------------------------------------------
extern "C" void kernel_launch(void* const* d_in, const int* in_sizes, int n_in,
                              void* d_out, int out_size) {
    const float* x     = (const float*)d_in[0];
    const int* ei      = (const int*)d_in[1];
    const float* ea    = (const float*)d_in[2];
    const float* We    = (const float*)d_in[3];
    const float* be    = (const float*)d_in[4];
    const float* eps   = (const float*)d_in[5];
    const float* W1    = (const float*)d_in[6];
    const float* b1    = (const float*)d_in[7];
    const float* gamma = (const float*)d_in[8];
    const float* beta  = (const float*)d_in[9];
    const float* W2    = (const float*)d_in[10];
    const float* b2    = (const float*)d_in[11];
    float* out         = (float*)d_out;

    float *hbuf, *ybuf;
    cudaGetSymbolAddress((void**)&hbuf, g_h);
    cudaGetSymbolAddress((void**)&ybuf, g_y);

    cudaFuncSetAttribute(gemm_hmma_kernel<0>, cudaFuncAttributeMaxDynamicSharedMemorySize, SMEM_BYTES);
    cudaFuncSetAttribute(gemm_hmma_kernel<1>, cudaFuncAttributeMaxDynamicSharedMemorySize, SMEM_BYTES);

    const int* src = ei;
    const int* dst = ei + NE;

    k_pre1<<<(NE + 255) / 256, 256>>>(dst, W1, W2);
    k_scan<<<NBLK, 256>>>();
    k_fill<<<(NE + 255) / 256, 256>>>(src, dst, ea);

    const int aggBlocks = (NN * 32 + 255) / 256;   // 12500

    for (int l = 0; l < NL; l++) {
        const float* h_in = (l == 0) ? x : hbuf;
        float* h_out = (l == NL - 1) ? out : hbuf;

        agg_kernel<<<aggBlocks, 256>>>(h_in, We + l * DD, be + l * DD, eps, l);

        gemm_hmma_kernel<0><<<GGRID, 256, SMEM_BYTES>>>(
            nullptr, l * 2, b1 + l * DD, nullptr, ybuf, 0, l, nullptr, nullptr);

        gemm_hmma_kernel<1><<<GGRID, 256, SMEM_BYTES>>>(
            ybuf, l * 2 + 1, b2 + l * DD, hbuf, h_out,
            (l > 0) ? 1 : 0, l, gamma + l * DD, beta + l * DD);
    }
}